// round 2
// baseline (speedup 1.0000x reference)
#include <cuda_runtime.h>
#include <cuda_bf16.h>
#include <math.h>

// Problem constants
#define Bv 2
#define Lv 2048
#define Tv 2048
#define Dv 1024
#define Hv 16
#define HDv 64

// Scratch (device globals: allocation-free rule)
__device__ float g_Q[Bv * Lv * Dv];        // 16 MB  [B*L, D]
__device__ float g_KV[Bv * Tv * 2 * Dv];   // 64 MB  [B*T, 2D]
__device__ float g_O[Bv * Lv * Dv];        // 16 MB  [B*L, D]

// ---------------- SGEMM + bias: C[M,N] = A[M,K] @ W[K,N] + b ----------------
#define BM 128
#define BN 128
#define BK 8
#define TM 8
#define TN 8

__global__ __launch_bounds__(256) void sgemm_bias(
    const float* __restrict__ A, const float* __restrict__ W,
    const float* __restrict__ bias, float* __restrict__ C,
    int M, int N, int K)
{
    __shared__ float As[BK][BM];
    __shared__ float Bs[BK][BN];

    const int tid = threadIdx.x;
    const int brow = blockIdx.y, bcol = blockIdx.x;
    const int threadRow = tid >> 4;      // 0..15
    const int threadCol = tid & 15;      // 0..15
    const int aRow = tid >> 1;           // 0..127
    const int aCol = (tid & 1) << 2;     // 0 or 4
    const int bRow = tid >> 5;           // 0..7
    const int bCol = (tid & 31) << 2;    // 0..124

    const float* Ab = A + (size_t)brow * BM * K;
    const float* Wb = W + (size_t)bcol * BN;

    float acc[TM][TN] = {};

    for (int k0 = 0; k0 < K; k0 += BK) {
        float4 a4 = *(const float4*)(Ab + (size_t)aRow * K + k0 + aCol);
        As[aCol + 0][aRow] = a4.x;
        As[aCol + 1][aRow] = a4.y;
        As[aCol + 2][aRow] = a4.z;
        As[aCol + 3][aRow] = a4.w;
        *(float4*)(&Bs[bRow][bCol]) =
            *(const float4*)(Wb + (size_t)(k0 + bRow) * N + bCol);
        __syncthreads();

        #pragma unroll
        for (int k = 0; k < BK; k++) {
            float regM[TM], regN[TN];
            *(float4*)(regM)     = *(const float4*)(&As[k][threadRow * TM]);
            *(float4*)(regM + 4) = *(const float4*)(&As[k][threadRow * TM + 4]);
            *(float4*)(regN)     = *(const float4*)(&Bs[k][threadCol * TN]);
            *(float4*)(regN + 4) = *(const float4*)(&Bs[k][threadCol * TN + 4]);
            #pragma unroll
            for (int i = 0; i < TM; i++)
                #pragma unroll
                for (int j = 0; j < TN; j++)
                    acc[i][j] += regM[i] * regN[j];
        }
        __syncthreads();
    }

    #pragma unroll
    for (int i = 0; i < TM; i++) {
        size_t row = (size_t)brow * BM + threadRow * TM + i;
        #pragma unroll
        for (int j = 0; j < TN; j += 4) {
            int col = bcol * BN + threadCol * TN + j;
            float4 bi = *(const float4*)(bias + col);
            float4 o4 = make_float4(acc[i][j] + bi.x, acc[i][j + 1] + bi.y,
                                    acc[i][j + 2] + bi.z, acc[i][j + 3] + bi.w);
            *(float4*)(C + row * N + col) = o4;
        }
    }
}

// ---------------- Flash attention (fp32, online softmax) ----------------
// Grid: (L/64, B*H). Block: 256 threads, each owns a 4x4 tile.
#define QLD 68
#define PLD 65
#define ATT_SMEM_FLOATS (3 * 64 * QLD + 64 * PLD + 4 * 64)

__global__ __launch_bounds__(256) void attn_kernel(
    const float* __restrict__ Q, const float* __restrict__ KV,
    const int* __restrict__ mask, float* __restrict__ Out)
{
    extern __shared__ float sm[];
    float* Qs    = sm;
    float* Ks    = Qs + 64 * QLD;
    float* Vs    = Ks + 64 * QLD;
    float* Ps    = Vs + 64 * QLD;
    float* rowm  = Ps + 64 * PLD;
    float* rowl  = rowm + 64;
    float* rowa  = rowl + 64;
    float* mflag = rowa + 64;

    const int tid = threadIdx.x;
    const int b = blockIdx.y >> 4;     // / H (H=16)
    const int h = blockIdx.y & 15;
    const int l0 = blockIdx.x << 6;
    const int tr = tid >> 4, tc = tid & 15;
    const int r0 = tr << 2, c0 = tc << 2;

    const float* Qg = Q + ((size_t)(b * Lv + l0)) * Dv + h * HDv;
    const float* Kg = KV + ((size_t)b * Tv) * (2 * Dv) + h * HDv;
    const float* Vg = Kg + Dv;
    const int* mg = mask + b * Tv;

    // Load Q tile, pre-scaled by 1/sqrt(HD) = 0.125
    #pragma unroll
    for (int it = 0; it < 4; it++) {
        int e = tid + it * 256;
        int r = e >> 4, dq = (e & 15) << 2;
        float4 q4 = *(const float4*)(Qg + (size_t)r * Dv + dq);
        q4.x *= 0.125f; q4.y *= 0.125f; q4.z *= 0.125f; q4.w *= 0.125f;
        *(float4*)(Qs + r * QLD + dq) = q4;
    }
    if (tid < 64) { rowm[tid] = -INFINITY; rowl[tid] = 0.f; }
    float o[4][4] = {};
    __syncthreads();

    for (int t0 = 0; t0 < Tv; t0 += 64) {
        // Load K/V chunks
        #pragma unroll
        for (int it = 0; it < 4; it++) {
            int e = tid + it * 256;
            int c = e >> 4, dq = (e & 15) << 2;
            *(float4*)(Ks + c * QLD + dq) =
                *(const float4*)(Kg + (size_t)(t0 + c) * (2 * Dv) + dq);
            *(float4*)(Vs + c * QLD + dq) =
                *(const float4*)(Vg + (size_t)(t0 + c) * (2 * Dv) + dq);
        }
        if (tid < 64) mflag[tid] = (mg[t0 + tid] != 0) ? 1.f : 0.f;
        __syncthreads();

        // S = Q K^T for this thread's 4x4 tile
        float s[4][4] = {};
        #pragma unroll
        for (int d4 = 0; d4 < HDv; d4 += 4) {
            float4 qv[4], kk[4];
            #pragma unroll
            for (int i = 0; i < 4; i++)
                qv[i] = *(const float4*)(Qs + (r0 + i) * QLD + d4);
            #pragma unroll
            for (int j = 0; j < 4; j++)
                kk[j] = *(const float4*)(Ks + (c0 + j) * QLD + d4);
            #pragma unroll
            for (int i = 0; i < 4; i++)
                #pragma unroll
                for (int j = 0; j < 4; j++)
                    s[i][j] += qv[i].x * kk[j].x + qv[i].y * kk[j].y +
                               qv[i].z * kk[j].z + qv[i].w * kk[j].w;
        }

        // Mask (replacement semantics, matching reference) + stage to smem
        #pragma unroll
        for (int j = 0; j < 4; j++) {
            bool valid = (mflag[c0 + j] != 0.f);
            #pragma unroll
            for (int i = 0; i < 4; i++)
                Ps[(r0 + i) * PLD + c0 + j] = valid ? s[i][j] : -1e9f;
        }
        __syncthreads();

        // Online softmax: one thread per row
        if (tid < 64) {
            float* pr = Ps + tid * PLD;
            float mo = rowm[tid], mx = mo;
            #pragma unroll 8
            for (int c = 0; c < 64; c++) mx = fmaxf(mx, pr[c]);
            float al = __expf(mo - mx);
            float sum = 0.f;
            #pragma unroll 8
            for (int c = 0; c < 64; c++) {
                float ev = __expf(pr[c] - mx);
                pr[c] = ev;
                sum += ev;
            }
            rowl[tid] = rowl[tid] * al + sum;
            rowm[tid] = mx;
            rowa[tid] = al;
        }
        __syncthreads();

        // Rescale O, accumulate P @ V
        float al[4];
        #pragma unroll
        for (int i = 0; i < 4; i++) al[i] = rowa[r0 + i];
        #pragma unroll
        for (int i = 0; i < 4; i++)
            #pragma unroll
            for (int j = 0; j < 4; j++) o[i][j] *= al[i];

        #pragma unroll 4
        for (int t = 0; t < 64; t++) {
            float4 v4 = *(const float4*)(Vs + t * QLD + c0);
            float p0 = Ps[(r0 + 0) * PLD + t];
            float p1 = Ps[(r0 + 1) * PLD + t];
            float p2 = Ps[(r0 + 2) * PLD + t];
            float p3 = Ps[(r0 + 3) * PLD + t];
            o[0][0] += p0 * v4.x; o[0][1] += p0 * v4.y; o[0][2] += p0 * v4.z; o[0][3] += p0 * v4.w;
            o[1][0] += p1 * v4.x; o[1][1] += p1 * v4.y; o[1][2] += p1 * v4.z; o[1][3] += p1 * v4.w;
            o[2][0] += p2 * v4.x; o[2][1] += p2 * v4.y; o[2][2] += p2 * v4.z; o[2][3] += p2 * v4.w;
            o[3][0] += p3 * v4.x; o[3][1] += p3 * v4.y; o[3][2] += p3 * v4.z; o[3][3] += p3 * v4.w;
        }
        __syncthreads();
    }

    // Normalize and write: Out[b, l, h*HD + d]
    float inv[4];
    #pragma unroll
    for (int i = 0; i < 4; i++) inv[i] = 1.0f / rowl[r0 + i];
    #pragma unroll
    for (int i = 0; i < 4; i++) {
        float4 o4 = make_float4(o[i][0] * inv[i], o[i][1] * inv[i],
                                o[i][2] * inv[i], o[i][3] * inv[i]);
        *(float4*)(Out + ((size_t)(b * Lv + l0 + r0 + i)) * Dv + h * HDv + c0) = o4;
    }
}

// ---------------- launch ----------------
extern "C" void kernel_launch(void* const* d_in, const int* in_sizes, int n_in,
                              void* d_out, int out_size)
{
    const float* x      = (const float*)d_in[0];
    const float* ctx    = (const float*)d_in[1];
    const int*   cmsk   = (const int*)d_in[2];
    const float* Wq     = (const float*)d_in[3];
    const float* bq     = (const float*)d_in[4];
    const float* Wkv    = (const float*)d_in[5];
    const float* bkv    = (const float*)d_in[6];
    const float* Wproj  = (const float*)d_in[7];
    const float* bproj  = (const float*)d_in[8];
    float* out          = (float*)d_out;

    float *Qp, *KVp, *Op;
    cudaGetSymbolAddress((void**)&Qp, g_Q);
    cudaGetSymbolAddress((void**)&KVp, g_KV);
    cudaGetSymbolAddress((void**)&Op, g_O);

    const size_t smem = (size_t)ATT_SMEM_FLOATS * sizeof(float);
    cudaFuncSetAttribute(attn_kernel,
                         cudaFuncAttributeMaxDynamicSharedMemorySize, (int)smem);

    dim3 blk(256);
    // Q = x @ Wq + bq            [4096,1024]
    sgemm_bias<<<dim3(Dv / BN, (Bv * Lv) / BM), blk>>>(x, Wq, bq, Qp,
                                                       Bv * Lv, Dv, Dv);
    // KV = ctx @ Wkv + bkv       [4096,2048]
    sgemm_bias<<<dim3((2 * Dv) / BN, (Bv * Tv) / BM), blk>>>(ctx, Wkv, bkv, KVp,
                                                             Bv * Tv, 2 * Dv, Dv);
    // attention                  -> g_O [4096,1024] (B,L,H*HD)
    attn_kernel<<<dim3(Lv / 64, Bv * Hv), blk, smem>>>(Qp, KVp, cmsk, Op);
    // out = O @ Wproj + bproj    [4096,1024]
    sgemm_bias<<<dim3(Dv / BN, (Bv * Lv) / BM), blk>>>(Op, Wproj, bproj, out,
                                                       Bv * Lv, Dv, Dv);
}

// round 3
// speedup vs baseline: 1.0000x; 1.0000x over previous
#include <cuda_runtime.h>
#include <cuda_bf16.h>
#include <math.h>

// Problem constants
#define Bv 2
#define Lv 2048
#define Tv 2048
#define Dv 1024
#define Hv 16
#define HDv 64

// Scratch (device globals: allocation-free rule)
__device__ float g_Q[Bv * Lv * Dv];        // 16 MB  [B*L, D]
__device__ float g_KV[Bv * Tv * 2 * Dv];   // 64 MB  [B*T, 2D]
__device__ float g_O[Bv * Lv * Dv];        // 16 MB  [B*L, D]

// ---------------- SGEMM + bias: C[M,N] = A[M,K] @ W[K,N] + b ----------------
#define BM 128
#define BN 128
#define BK 8
#define TM 8
#define TN 8

__global__ __launch_bounds__(256) void sgemm_bias(
    const float* __restrict__ A, const float* __restrict__ W,
    const float* __restrict__ bias, float* __restrict__ C,
    int M, int N, int K)
{
    __shared__ float As[BK][BM];
    __shared__ float Bs[BK][BN];

    const int tid = threadIdx.x;
    const int brow = blockIdx.y, bcol = blockIdx.x;
    const int threadRow = tid >> 4;      // 0..15
    const int threadCol = tid & 15;      // 0..15
    const int aRow = tid >> 1;           // 0..127
    const int aCol = (tid & 1) << 2;     // 0 or 4
    const int bRow = tid >> 5;           // 0..7
    const int bCol = (tid & 31) << 2;    // 0..124

    const float* Ab = A + (size_t)brow * BM * K;
    const float* Wb = W + (size_t)bcol * BN;

    float acc[TM][TN] = {};

    for (int k0 = 0; k0 < K; k0 += BK) {
        float4 a4 = *(const float4*)(Ab + (size_t)aRow * K + k0 + aCol);
        As[aCol + 0][aRow] = a4.x;
        As[aCol + 1][aRow] = a4.y;
        As[aCol + 2][aRow] = a4.z;
        As[aCol + 3][aRow] = a4.w;
        *(float4*)(&Bs[bRow][bCol]) =
            *(const float4*)(Wb + (size_t)(k0 + bRow) * N + bCol);
        __syncthreads();

        #pragma unroll
        for (int k = 0; k < BK; k++) {
            float regM[TM], regN[TN];
            *(float4*)(regM)     = *(const float4*)(&As[k][threadRow * TM]);
            *(float4*)(regM + 4) = *(const float4*)(&As[k][threadRow * TM + 4]);
            *(float4*)(regN)     = *(const float4*)(&Bs[k][threadCol * TN]);
            *(float4*)(regN + 4) = *(const float4*)(&Bs[k][threadCol * TN + 4]);
            #pragma unroll
            for (int i = 0; i < TM; i++)
                #pragma unroll
                for (int j = 0; j < TN; j++)
                    acc[i][j] += regM[i] * regN[j];
        }
        __syncthreads();
    }

    #pragma unroll
    for (int i = 0; i < TM; i++) {
        size_t row = (size_t)brow * BM + threadRow * TM + i;
        #pragma unroll
        for (int j = 0; j < TN; j += 4) {
            int col = bcol * BN + threadCol * TN + j;
            float4 bi = *(const float4*)(bias + col);
            float4 o4 = make_float4(acc[i][j] + bi.x, acc[i][j + 1] + bi.y,
                                    acc[i][j + 2] + bi.z, acc[i][j + 3] + bi.w);
            *(float4*)(C + row * N + col) = o4;
        }
    }
}

// ---------------- Flash attention (fp32, online softmax) ----------------
// Grid: (L/64, B*H). Block: 256 threads, each owns a 4x4 tile.
#define QLD 68
#define PLD 65
#define ATT_SMEM_FLOATS (3 * 64 * QLD + 64 * PLD + 4 * 64)

__global__ __launch_bounds__(256) void attn_kernel(
    const float* __restrict__ Q, const float* __restrict__ KV,
    const int* __restrict__ mask, float* __restrict__ Out)
{
    extern __shared__ float sm[];
    float* Qs    = sm;
    float* Ks    = Qs + 64 * QLD;
    float* Vs    = Ks + 64 * QLD;
    float* Ps    = Vs + 64 * QLD;
    float* rowm  = Ps + 64 * PLD;
    float* rowl  = rowm + 64;
    float* rowa  = rowl + 64;
    float* mflag = rowa + 64;

    const int tid = threadIdx.x;
    const int b = blockIdx.y >> 4;     // / H (H=16)
    const int h = blockIdx.y & 15;
    const int l0 = blockIdx.x << 6;
    const int tr = tid >> 4, tc = tid & 15;
    const int r0 = tr << 2, c0 = tc << 2;

    const float* Qg = Q + ((size_t)(b * Lv + l0)) * Dv + h * HDv;
    const float* Kg = KV + ((size_t)b * Tv) * (2 * Dv) + h * HDv;
    const float* Vg = Kg + Dv;
    const int* mg = mask + b * Tv;

    // Load Q tile, pre-scaled by 1/sqrt(HD) = 0.125
    #pragma unroll
    for (int it = 0; it < 4; it++) {
        int e = tid + it * 256;
        int r = e >> 4, dq = (e & 15) << 2;
        float4 q4 = *(const float4*)(Qg + (size_t)r * Dv + dq);
        q4.x *= 0.125f; q4.y *= 0.125f; q4.z *= 0.125f; q4.w *= 0.125f;
        *(float4*)(Qs + r * QLD + dq) = q4;
    }
    if (tid < 64) { rowm[tid] = -INFINITY; rowl[tid] = 0.f; }
    float o[4][4] = {};
    __syncthreads();

    for (int t0 = 0; t0 < Tv; t0 += 64) {
        // Load K/V chunks
        #pragma unroll
        for (int it = 0; it < 4; it++) {
            int e = tid + it * 256;
            int c = e >> 4, dq = (e & 15) << 2;
            *(float4*)(Ks + c * QLD + dq) =
                *(const float4*)(Kg + (size_t)(t0 + c) * (2 * Dv) + dq);
            *(float4*)(Vs + c * QLD + dq) =
                *(const float4*)(Vg + (size_t)(t0 + c) * (2 * Dv) + dq);
        }
        if (tid < 64) mflag[tid] = (mg[t0 + tid] != 0) ? 1.f : 0.f;
        __syncthreads();

        // S = Q K^T for this thread's 4x4 tile
        float s[4][4] = {};
        #pragma unroll
        for (int d4 = 0; d4 < HDv; d4 += 4) {
            float4 qv[4], kk[4];
            #pragma unroll
            for (int i = 0; i < 4; i++)
                qv[i] = *(const float4*)(Qs + (r0 + i) * QLD + d4);
            #pragma unroll
            for (int j = 0; j < 4; j++)
                kk[j] = *(const float4*)(Ks + (c0 + j) * QLD + d4);
            #pragma unroll
            for (int i = 0; i < 4; i++)
                #pragma unroll
                for (int j = 0; j < 4; j++)
                    s[i][j] += qv[i].x * kk[j].x + qv[i].y * kk[j].y +
                               qv[i].z * kk[j].z + qv[i].w * kk[j].w;
        }

        // Mask (replacement semantics, matching reference) + stage to smem
        #pragma unroll
        for (int j = 0; j < 4; j++) {
            bool valid = (mflag[c0 + j] != 0.f);
            #pragma unroll
            for (int i = 0; i < 4; i++)
                Ps[(r0 + i) * PLD + c0 + j] = valid ? s[i][j] : -1e9f;
        }
        __syncthreads();

        // Online softmax: one thread per row
        if (tid < 64) {
            float* pr = Ps + tid * PLD;
            float mo = rowm[tid], mx = mo;
            #pragma unroll 8
            for (int c = 0; c < 64; c++) mx = fmaxf(mx, pr[c]);
            float al = __expf(mo - mx);
            float sum = 0.f;
            #pragma unroll 8
            for (int c = 0; c < 64; c++) {
                float ev = __expf(pr[c] - mx);
                pr[c] = ev;
                sum += ev;
            }
            rowl[tid] = rowl[tid] * al + sum;
            rowm[tid] = mx;
            rowa[tid] = al;
        }
        __syncthreads();

        // Rescale O, accumulate P @ V
        float al[4];
        #pragma unroll
        for (int i = 0; i < 4; i++) al[i] = rowa[r0 + i];
        #pragma unroll
        for (int i = 0; i < 4; i++)
            #pragma unroll
            for (int j = 0; j < 4; j++) o[i][j] *= al[i];

        #pragma unroll 4
        for (int t = 0; t < 64; t++) {
            float4 v4 = *(const float4*)(Vs + t * QLD + c0);
            float p0 = Ps[(r0 + 0) * PLD + t];
            float p1 = Ps[(r0 + 1) * PLD + t];
            float p2 = Ps[(r0 + 2) * PLD + t];
            float p3 = Ps[(r0 + 3) * PLD + t];
            o[0][0] += p0 * v4.x; o[0][1] += p0 * v4.y; o[0][2] += p0 * v4.z; o[0][3] += p0 * v4.w;
            o[1][0] += p1 * v4.x; o[1][1] += p1 * v4.y; o[1][2] += p1 * v4.z; o[1][3] += p1 * v4.w;
            o[2][0] += p2 * v4.x; o[2][1] += p2 * v4.y; o[2][2] += p2 * v4.z; o[2][3] += p2 * v4.w;
            o[3][0] += p3 * v4.x; o[3][1] += p3 * v4.y; o[3][2] += p3 * v4.z; o[3][3] += p3 * v4.w;
        }
        __syncthreads();
    }

    // Normalize and write: Out[b, l, h*HD + d]
    float inv[4];
    #pragma unroll
    for (int i = 0; i < 4; i++) inv[i] = 1.0f / rowl[r0 + i];
    #pragma unroll
    for (int i = 0; i < 4; i++) {
        float4 o4 = make_float4(o[i][0] * inv[i], o[i][1] * inv[i],
                                o[i][2] * inv[i], o[i][3] * inv[i]);
        *(float4*)(Out + ((size_t)(b * Lv + l0 + r0 + i)) * Dv + h * HDv + c0) = o4;
    }
}

// ---------------- launch ----------------
extern "C" void kernel_launch(void* const* d_in, const int* in_sizes, int n_in,
                              void* d_out, int out_size)
{
    const float* x      = (const float*)d_in[0];
    const float* ctx    = (const float*)d_in[1];
    const int*   cmsk   = (const int*)d_in[2];
    const float* Wq     = (const float*)d_in[3];
    const float* bq     = (const float*)d_in[4];
    const float* Wkv    = (const float*)d_in[5];
    const float* bkv    = (const float*)d_in[6];
    const float* Wproj  = (const float*)d_in[7];
    const float* bproj  = (const float*)d_in[8];
    float* out          = (float*)d_out;

    float *Qp, *KVp, *Op;
    cudaGetSymbolAddress((void**)&Qp, g_Q);
    cudaGetSymbolAddress((void**)&KVp, g_KV);
    cudaGetSymbolAddress((void**)&Op, g_O);

    const size_t smem = (size_t)ATT_SMEM_FLOATS * sizeof(float);
    cudaFuncSetAttribute(attn_kernel,
                         cudaFuncAttributeMaxDynamicSharedMemorySize, (int)smem);

    dim3 blk(256);
    // Q = x @ Wq + bq            [4096,1024]
    sgemm_bias<<<dim3(Dv / BN, (Bv * Lv) / BM), blk>>>(x, Wq, bq, Qp,
                                                       Bv * Lv, Dv, Dv);
    // KV = ctx @ Wkv + bkv       [4096,2048]
    sgemm_bias<<<dim3((2 * Dv) / BN, (Bv * Tv) / BM), blk>>>(ctx, Wkv, bkv, KVp,
                                                             Bv * Tv, 2 * Dv, Dv);
    // attention                  -> g_O [4096,1024] (B,L,H*HD)
    attn_kernel<<<dim3(Lv / 64, Bv * Hv), blk, smem>>>(Qp, KVp, cmsk, Op);
    // out = O @ Wproj + bproj    [4096,1024]
    sgemm_bias<<<dim3(Dv / BN, (Bv * Lv) / BM), blk>>>(Op, Wproj, bproj, out,
                                                       Bv * Lv, Dv, Dv);
}

// round 5
// speedup vs baseline: 2.8366x; 2.8365x over previous
#include <cuda_runtime.h>
#include <cuda_bf16.h>
#include <math.h>
#include <stdint.h>

#define Bv 2
#define Lv 2048
#define Tv 2048
#define Dv 1024
#define Hv 16
#define HDv 64
#define BHv (Bv*Hv)
typedef __nv_bfloat16 bf16;

// ---------------- scratch ----------------
__device__ bf16 g_xh[Bv*Lv*Dv], g_xl[Bv*Lv*Dv];
__device__ bf16 g_ch[Bv*Tv*Dv], g_cl[Bv*Tv*Dv];
__device__ bf16 g_Wqh[Dv*Dv],   g_Wql[Dv*Dv];        // [N][K]
__device__ bf16 g_Wkh[2*Dv*Dv], g_Wkl[2*Dv*Dv];
__device__ bf16 g_Wph[Dv*Dv],   g_Wpl[Dv*Dv];
__device__ bf16 g_Qh[BHv*Lv*HDv], g_Ql[BHv*Lv*HDv]; // [bh][l][hd] (scaled 0.125)
__device__ bf16 g_Kh[BHv*Tv*HDv], g_Kl[BHv*Tv*HDv];
__device__ bf16 g_Vh[BHv*Tv*HDv], g_Vl[BHv*Tv*HDv];
__device__ bf16 g_Vth[BHv*HDv*Tv], g_Vtl[BHv*HDv*Tv]; // [bh][hd][t]
__device__ bf16 g_Oh[Bv*Lv*Dv], g_Ol[Bv*Lv*Dv];     // [b*l][D]

// ---------------- helpers ----------------
__device__ __forceinline__ void bsplit(float x, unsigned short &h, unsigned short &l){
    bf16 hb = __float2bfloat16_rn(x);
    bf16 lb = __float2bfloat16_rn(x - __bfloat162float(hb));
    h = __bfloat16_as_ushort(hb); l = __bfloat16_as_ushort(lb);
}
__device__ __forceinline__ void pksplit(float a, float b, unsigned &hi, unsigned &lo){
    unsigned short h0,l0,h1,l1; bsplit(a,h0,l0); bsplit(b,h1,l1);
    hi = (unsigned)h0 | ((unsigned)h1<<16); lo = (unsigned)l0 | ((unsigned)l1<<16);
}
__device__ __forceinline__ void mma_bf16(float c[4], const unsigned a[4], const unsigned b[2]){
    asm volatile("mma.sync.aligned.m16n8k16.row.col.f32.bf16.bf16.f32 "
        "{%0,%1,%2,%3}, {%4,%5,%6,%7}, {%8,%9}, {%0,%1,%2,%3};"
        : "+f"(c[0]), "+f"(c[1]), "+f"(c[2]), "+f"(c[3])
        : "r"(a[0]), "r"(a[1]), "r"(a[2]), "r"(a[3]), "r"(b[0]), "r"(b[1]));
}

// ---------------- prep kernels ----------------
__global__ void fsplit(const float* __restrict__ in, bf16* __restrict__ h, bf16* __restrict__ l, int n){
    int i = blockIdx.x*256 + threadIdx.x;
    if (i < n){ unsigned short a,b; bsplit(in[i],a,b); h[i]=__ushort_as_bfloat16(a); l[i]=__ushort_as_bfloat16(b); }
}
__global__ void wprep(const float* __restrict__ W, bf16* __restrict__ th, bf16* __restrict__ tl, int N){
    __shared__ float t[32][33];
    int k0 = blockIdx.y*32, n0 = blockIdx.x*32, tx = threadIdx.x, ty = threadIdx.y;
    #pragma unroll
    for (int j=0;j<4;j++) t[ty+j*8][tx] = W[(size_t)(k0+ty+j*8)*N + n0+tx];
    __syncthreads();
    #pragma unroll
    for (int j=0;j<4;j++){
        unsigned short h,l; bsplit(t[tx][ty+j*8], h, l);
        size_t o = (size_t)(n0+ty+j*8)*Dv + k0+tx;
        th[o]=__ushort_as_bfloat16(h); tl[o]=__ushort_as_bfloat16(l);
    }
}
__global__ void vtrans(){
    __shared__ bf16 t[32][33];
    int bh = blockIdx.z, t0 = blockIdx.x*32, hd0 = blockIdx.y*32, tx = threadIdx.x, ty = threadIdx.y;
    for (int plane=0; plane<2; plane++){
        const bf16* src = plane ? g_Vl : g_Vh;
        bf16* dst = plane ? g_Vtl : g_Vth;
        #pragma unroll
        for (int j=0;j<4;j++) t[ty+j*8][tx] = src[((size_t)bh*Tv + t0+ty+j*8)*HDv + hd0+tx];
        __syncthreads();
        #pragma unroll
        for (int j=0;j<4;j++) dst[((size_t)bh*HDv + hd0+ty+j*8)*Tv + t0+tx] = t[tx][ty+j*8];
        __syncthreads();
    }
}

// ---------------- HMMA GEMM: C[4096, N] = A[.,1024] @ W^T + bias ----------------
// A planes row-major [m][1024]; W planes [n][1024]. Tile 128x128, BK=32.
// mode 0: fp32 out; mode 1: Q planes (scale 0.125); mode 2: K/V planes.
#define GLD 40
__global__ __launch_bounds__(256,1) void hgemm(
    const bf16* __restrict__ Agh, const bf16* __restrict__ Agl,
    const bf16* __restrict__ Wgh, const bf16* __restrict__ Wgl,
    const float* __restrict__ bias, int mode, float* __restrict__ outf)
{
    __shared__ bf16 smA[2*128*GLD];
    __shared__ bf16 smB[2*128*GLD];
    const int tid = threadIdx.x, lane = tid&31, warp = tid>>5;
    const int g = lane>>2, tig = lane&3;
    const int wm = warp>>2, wn = warp&3;
    const int m0 = blockIdx.y*128, n0 = blockIdx.x*128;

    float acc[4][4][4] = {};
    uint4 pf[8];

    // prefetch chunk 0
    #pragma unroll
    for (int t=0;t<8;t++){
        int i = tid + t*256, plane = i>>9, w = i&511, row = w>>2, c4 = (w&3)*8;
        const bf16* src = plane==0?Agh : plane==1?Agl : plane==2?Wgh : Wgl;
        int grow = (plane<2?m0:n0) + row;
        pf[t] = *(const uint4*)(src + (size_t)grow*1024 + 0 + c4);
    }
    #pragma unroll
    for (int t=0;t<8;t++){
        int i = tid + t*256, plane = i>>9, w = i&511, row = w>>2, c4 = (w&3)*8;
        bf16* dst = (plane<2?smA:smB) + (plane&1)*(128*GLD) + row*GLD + c4;
        *(uint4*)dst = pf[t];
    }
    __syncthreads();

    for (int kb=0; kb<32; kb++){
        if (kb < 31){
            int k0 = (kb+1)*32;
            #pragma unroll
            for (int t=0;t<8;t++){
                int i = tid + t*256, plane = i>>9, w = i&511, row = w>>2, c4 = (w&3)*8;
                const bf16* src = plane==0?Agh : plane==1?Agl : plane==2?Wgh : Wgl;
                int grow = (plane<2?m0:n0) + row;
                pf[t] = *(const uint4*)(src + (size_t)grow*1024 + k0 + c4);
            }
        }
        #pragma unroll
        for (int ks=0; ks<2; ks++){
            const int kofs = ks*16 + 2*tig;
            unsigned ah[4][4], al[4][4], bh[4][2], bl[4][2];
            #pragma unroll
            for (int mt=0;mt<4;mt++){
                int r = wm*64 + mt*16 + g;
                ah[mt][0] = *(const unsigned*)(smA + r*GLD + kofs);
                ah[mt][1] = *(const unsigned*)(smA + (r+8)*GLD + kofs);
                ah[mt][2] = *(const unsigned*)(smA + r*GLD + kofs + 8);
                ah[mt][3] = *(const unsigned*)(smA + (r+8)*GLD + kofs + 8);
                al[mt][0] = *(const unsigned*)(smA + 128*GLD + r*GLD + kofs);
                al[mt][1] = *(const unsigned*)(smA + 128*GLD + (r+8)*GLD + kofs);
                al[mt][2] = *(const unsigned*)(smA + 128*GLD + r*GLD + kofs + 8);
                al[mt][3] = *(const unsigned*)(smA + 128*GLD + (r+8)*GLD + kofs + 8);
            }
            #pragma unroll
            for (int nt=0;nt<4;nt++){
                int r = wn*32 + nt*8 + g;
                bh[nt][0] = *(const unsigned*)(smB + r*GLD + kofs);
                bh[nt][1] = *(const unsigned*)(smB + r*GLD + kofs + 8);
                bl[nt][0] = *(const unsigned*)(smB + 128*GLD + r*GLD + kofs);
                bl[nt][1] = *(const unsigned*)(smB + 128*GLD + r*GLD + kofs + 8);
            }
            #pragma unroll
            for (int mt=0;mt<4;mt++)
                #pragma unroll
                for (int nt=0;nt<4;nt++){
                    mma_bf16(acc[mt][nt], ah[mt], bh[nt]);
                    mma_bf16(acc[mt][nt], ah[mt], bl[nt]);
                    mma_bf16(acc[mt][nt], al[mt], bh[nt]);
                }
        }
        __syncthreads();
        if (kb < 31){
            #pragma unroll
            for (int t=0;t<8;t++){
                int i = tid + t*256, plane = i>>9, w = i&511, row = w>>2, c4 = (w&3)*8;
                bf16* dst = (plane<2?smA:smB) + (plane&1)*(128*GLD) + row*GLD + c4;
                *(uint4*)dst = pf[t];
            }
            __syncthreads();
        }
    }

    // epilogue
    #pragma unroll
    for (int mt=0;mt<4;mt++){
        #pragma unroll
        for (int nt=0;nt<4;nt++){
            int r = m0 + wm*64 + mt*16 + g;
            int c = n0 + wn*32 + nt*8 + 2*tig;
            float v00 = acc[mt][nt][0] + bias[c];
            float v01 = acc[mt][nt][1] + bias[c+1];
            float v10 = acc[mt][nt][2] + bias[c];
            float v11 = acc[mt][nt][3] + bias[c+1];
            if (mode == 0){
                *(float2*)(outf + (size_t)r*1024 + c)      = make_float2(v00, v01);
                *(float2*)(outf + (size_t)(r+8)*1024 + c)  = make_float2(v10, v11);
            } else {
                int n2 = c, half = 0;
                if (mode == 2 && c >= 1024){ n2 = c - 1024; half = 1; }
                int h = n2>>6, hd = n2&63;
                bf16 *ph, *pl2;
                if (mode == 1){ ph = g_Qh; pl2 = g_Ql; }
                else if (!half){ ph = g_Kh; pl2 = g_Kl; }
                else { ph = g_Vh; pl2 = g_Vl; }
                float sc = (mode==1) ? 0.125f : 1.0f;
                #pragma unroll
                for (int rr=0; rr<2; rr++){
                    int m = r + rr*8;
                    int b = m>>11, l = m&2047;
                    size_t base = ((size_t)(b*16 + h)*2048 + l)*64 + hd;
                    unsigned hi, lo;
                    pksplit((rr?v10:v00)*sc, (rr?v11:v01)*sc, hi, lo);
                    *(unsigned*)(ph  + base) = hi;
                    *(unsigned*)(pl2 + base) = lo;
                }
            }
        }
    }
}

// ---------------- HMMA flash attention ----------------
// CTA: 128 thr (4 warps), 64 q-rows; chunks of 64 t.
#define ALD 72
#define QH_O 0
#define QL_O (64*ALD)
#define KH_O (2*64*ALD)
#define KL_O (3*64*ALD)
#define VH_O (4*64*ALD)
#define VL_O (5*64*ALD)
#define SM_BF (6*64*ALD)
#define ATT_SMEM (SM_BF*2 + 64*4)

__global__ __launch_bounds__(128,3) void hattn(const int* __restrict__ mask)
{
    extern __shared__ bf16 sm[];
    float* mflag = (float*)(sm + SM_BF);
    const int tid = threadIdx.x, lane = tid&31, warp = tid>>5;
    const int g = lane>>2, tig = lane&3;
    const int bh = blockIdx.y, b = bh>>4, h = bh&15, l0 = blockIdx.x*64;
    const int* mg = mask + b*Tv;

    // load Q planes [64][64] -> smem
    #pragma unroll
    for (int t=0;t<8;t++){
        int i = tid + t*128, plane = i>>9, w = i&511, row = w>>3, c8 = (w&7)*8;
        const bf16* src = plane ? g_Ql : g_Qh;
        uint4 v = *(const uint4*)(src + ((size_t)bh*Lv + l0 + row)*64 + c8);
        *(uint4*)(sm + (plane?QL_O:QH_O) + row*ALD + c8) = v;
    }
    __syncthreads();

    // preload Q fragments (resident whole kernel)
    unsigned qa[4][2][4];
    {
        int r = warp*16 + g;
        #pragma unroll
        for (int kk=0; kk<4; kk++){
            int kofs = kk*16 + 2*tig;
            #pragma unroll
            for (int p=0; p<2; p++){
                const bf16* q = sm + (p?QL_O:QH_O);
                qa[kk][p][0] = *(const unsigned*)(q + r*ALD + kofs);
                qa[kk][p][1] = *(const unsigned*)(q + (r+8)*ALD + kofs);
                qa[kk][p][2] = *(const unsigned*)(q + r*ALD + kofs + 8);
                qa[kk][p][3] = *(const unsigned*)(q + (r+8)*ALD + kofs + 8);
            }
        }
    }
    __syncthreads();

    float mold[2] = {-INFINITY, -INFINITY};
    float lsum[2] = {0.f, 0.f};
    float o[8][4] = {};

    for (int t0=0; t0<Tv; t0+=64){
        // load K [t][hd] and Vt [hd][t] planes
        #pragma unroll
        for (int t=0;t<16;t++){
            int i = tid + t*128, plane = i>>9, w = i&511, row = w>>3, c8 = (w&7)*8;
            uint4 v;
            if (plane == 0)      v = *(const uint4*)(g_Kh  + ((size_t)bh*Tv + t0 + row)*64 + c8);
            else if (plane == 1) v = *(const uint4*)(g_Kl  + ((size_t)bh*Tv + t0 + row)*64 + c8);
            else if (plane == 2) v = *(const uint4*)(g_Vth + ((size_t)bh*HDv + row)*Tv + t0 + c8);
            else                 v = *(const uint4*)(g_Vtl + ((size_t)bh*HDv + row)*Tv + t0 + c8);
            *(uint4*)(sm + KH_O + plane*(64*ALD) + row*ALD + c8) = v;
        }
        if (tid < 64) mflag[tid] = (mg[t0+tid] != 0) ? 1.f : 0.f;
        __syncthreads();

        // S = Q K^T  (split: QhKh + QhKl + QlKh), n over 64 t
        float s[8][4] = {};
        #pragma unroll
        for (int kk=0; kk<4; kk++){
            int kofs = kk*16 + 2*tig;
            unsigned bhf[8][2], blf[8][2];
            #pragma unroll
            for (int nt=0; nt<8; nt++){
                int r = nt*8 + g;
                bhf[nt][0] = *(const unsigned*)(sm + KH_O + r*ALD + kofs);
                bhf[nt][1] = *(const unsigned*)(sm + KH_O + r*ALD + kofs + 8);
                blf[nt][0] = *(const unsigned*)(sm + KL_O + r*ALD + kofs);
                blf[nt][1] = *(const unsigned*)(sm + KL_O + r*ALD + kofs + 8);
            }
            #pragma unroll
            for (int nt=0; nt<8; nt++){
                mma_bf16(s[nt], qa[kk][0], bhf[nt]);
                mma_bf16(s[nt], qa[kk][0], blf[nt]);
                mma_bf16(s[nt], qa[kk][1], bhf[nt]);
            }
        }

        // mask + online softmax on fragments (rows: g and g+8)
        float ma = mold[0], mb = mold[1];
        #pragma unroll
        for (int nt=0; nt<8; nt++){
            int c = nt*8 + 2*tig;
            if (mflag[c]   == 0.f){ s[nt][0] = -1e9f; s[nt][2] = -1e9f; }
            if (mflag[c+1] == 0.f){ s[nt][1] = -1e9f; s[nt][3] = -1e9f; }
            ma = fmaxf(ma, fmaxf(s[nt][0], s[nt][1]));
            mb = fmaxf(mb, fmaxf(s[nt][2], s[nt][3]));
        }
        ma = fmaxf(ma, __shfl_xor_sync(0xffffffffu, ma, 1));
        ma = fmaxf(ma, __shfl_xor_sync(0xffffffffu, ma, 2));
        mb = fmaxf(mb, __shfl_xor_sync(0xffffffffu, mb, 1));
        mb = fmaxf(mb, __shfl_xor_sync(0xffffffffu, mb, 2));

        float aa = __expf(mold[0] - ma), ab = __expf(mold[1] - mb);
        float suma = 0.f, sumb = 0.f;
        #pragma unroll
        for (int nt=0; nt<8; nt++){
            s[nt][0] = __expf(s[nt][0] - ma);
            s[nt][1] = __expf(s[nt][1] - ma);
            s[nt][2] = __expf(s[nt][2] - mb);
            s[nt][3] = __expf(s[nt][3] - mb);
            suma += s[nt][0] + s[nt][1];
            sumb += s[nt][2] + s[nt][3];
        }
        suma += __shfl_xor_sync(0xffffffffu, suma, 1);
        suma += __shfl_xor_sync(0xffffffffu, suma, 2);
        sumb += __shfl_xor_sync(0xffffffffu, sumb, 1);
        sumb += __shfl_xor_sync(0xffffffffu, sumb, 2);
        lsum[0] = lsum[0]*aa + suma;  mold[0] = ma;
        lsum[1] = lsum[1]*ab + sumb;  mold[1] = mb;
        #pragma unroll
        for (int nt=0; nt<8; nt++){
            o[nt][0] *= aa; o[nt][1] *= aa; o[nt][2] *= ab; o[nt][3] *= ab;
        }

        // PV: P (C-frag -> A-frag identity), V from Vt[hd][t]
        #pragma unroll
        for (int kt=0; kt<4; kt++){
            unsigned pah[4], pal[4];
            pksplit(s[2*kt][0],   s[2*kt][1],   pah[0], pal[0]);
            pksplit(s[2*kt][2],   s[2*kt][3],   pah[1], pal[1]);
            pksplit(s[2*kt+1][0], s[2*kt+1][1], pah[2], pal[2]);
            pksplit(s[2*kt+1][2], s[2*kt+1][3], pah[3], pal[3]);
            int kofs = kt*16 + 2*tig;
            #pragma unroll
            for (int nt=0; nt<8; nt++){
                int r = nt*8 + g;
                unsigned vh[2], vl[2];
                vh[0] = *(const unsigned*)(sm + VH_O + r*ALD + kofs);
                vh[1] = *(const unsigned*)(sm + VH_O + r*ALD + kofs + 8);
                vl[0] = *(const unsigned*)(sm + VL_O + r*ALD + kofs);
                vl[1] = *(const unsigned*)(sm + VL_O + r*ALD + kofs + 8);
                mma_bf16(o[nt], pah, vh);
                mma_bf16(o[nt], pah, vl);
                mma_bf16(o[nt], pal, vh);
            }
        }
        __syncthreads();
    }

    // normalize + write split O planes
    float inva = 1.0f / lsum[0], invb = 1.0f / lsum[1];
    int ra = l0 + warp*16 + g, rb = ra + 8;
    #pragma unroll
    for (int nt=0; nt<8; nt++){
        int c = h*64 + nt*8 + 2*tig;
        unsigned hi, lo;
        size_t basea = ((size_t)(b*Lv + ra))*Dv + c;
        pksplit(o[nt][0]*inva, o[nt][1]*inva, hi, lo);
        *(unsigned*)(g_Oh + basea) = hi;
        *(unsigned*)(g_Ol + basea) = lo;
        size_t baseb = ((size_t)(b*Lv + rb))*Dv + c;
        pksplit(o[nt][2]*invb, o[nt][3]*invb, hi, lo);
        *(unsigned*)(g_Oh + baseb) = hi;
        *(unsigned*)(g_Ol + baseb) = lo;
    }
}

// ---------------- launch ----------------
extern "C" void kernel_launch(void* const* d_in, const int* in_sizes, int n_in,
                              void* d_out, int out_size)
{
    const float* x     = (const float*)d_in[0];
    const float* ctx   = (const float*)d_in[1];
    const int*   cmsk  = (const int*)d_in[2];
    const float* Wq    = (const float*)d_in[3];
    const float* bq    = (const float*)d_in[4];
    const float* Wkv   = (const float*)d_in[5];
    const float* bkv   = (const float*)d_in[6];
    const float* Wproj = (const float*)d_in[7];
    const float* bproj = (const float*)d_in[8];
    float* out         = (float*)d_out;

    bf16 *xh,*xl,*ch,*cl,*wqh,*wql,*wkh,*wkl,*wph,*wpl,*oh,*ol;
    cudaGetSymbolAddress((void**)&xh, g_xh);   cudaGetSymbolAddress((void**)&xl, g_xl);
    cudaGetSymbolAddress((void**)&ch, g_ch);   cudaGetSymbolAddress((void**)&cl, g_cl);
    cudaGetSymbolAddress((void**)&wqh, g_Wqh); cudaGetSymbolAddress((void**)&wql, g_Wql);
    cudaGetSymbolAddress((void**)&wkh, g_Wkh); cudaGetSymbolAddress((void**)&wkl, g_Wkl);
    cudaGetSymbolAddress((void**)&wph, g_Wph); cudaGetSymbolAddress((void**)&wpl, g_Wpl);
    cudaGetSymbolAddress((void**)&oh, g_Oh);   cudaGetSymbolAddress((void**)&ol, g_Ol);

    cudaFuncSetAttribute(hattn, cudaFuncAttributeMaxDynamicSharedMemorySize, ATT_SMEM);

    const int NM = Bv*Lv;  // 4096

    fsplit<<<NM*Dv/256, 256>>>(x, xh, xl, NM*Dv);
    fsplit<<<NM*Dv/256, 256>>>(ctx, ch, cl, NM*Dv);
    wprep<<<dim3(Dv/32, Dv/32), dim3(32,8)>>>(Wq, wqh, wql, Dv);
    wprep<<<dim3(2*Dv/32, Dv/32), dim3(32,8)>>>(Wkv, wkh, wkl, 2*Dv);
    wprep<<<dim3(Dv/32, Dv/32), dim3(32,8)>>>(Wproj, wph, wpl, Dv);

    hgemm<<<dim3(Dv/128, NM/128), 256>>>(xh, xl, wqh, wql, bq, 1, nullptr);
    hgemm<<<dim3(2*Dv/128, NM/128), 256>>>(ch, cl, wkh, wkl, bkv, 2, nullptr);
    vtrans<<<dim3(Tv/32, HDv/32, BHv), dim3(32,8)>>>();
    hattn<<<dim3(Lv/64, BHv), 128, ATT_SMEM>>>(cmsk);
    hgemm<<<dim3(Dv/128, NM/128), 256>>>(oh, ol, wph, wpl, bproj, 0, out);
}

// round 6
// speedup vs baseline: 3.0740x; 1.0837x over previous
#include <cuda_runtime.h>
#include <cuda_bf16.h>
#include <math.h>
#include <stdint.h>

#define Bv 2
#define Lv 2048
#define Tv 2048
#define Dv 1024
#define Hv 16
#define HDv 64
#define BHv (Bv*Hv)
typedef __nv_bfloat16 bf16;

// ---------------- scratch ----------------
__device__ bf16 g_xh[Bv*Lv*Dv], g_xl[Bv*Lv*Dv];
__device__ bf16 g_ch[Bv*Tv*Dv], g_cl[Bv*Tv*Dv];
__device__ bf16 g_Wqh[Dv*Dv],   g_Wql[Dv*Dv];        // [N][K]
__device__ bf16 g_Wkh[2*Dv*Dv], g_Wkl[2*Dv*Dv];
__device__ bf16 g_Wph[Dv*Dv],   g_Wpl[Dv*Dv];
__device__ bf16 g_Qh[BHv*Lv*HDv], g_Ql[BHv*Lv*HDv]; // [bh][l][hd] (scaled 0.125)
__device__ bf16 g_Kh[BHv*Tv*HDv], g_Kl[BHv*Tv*HDv];
__device__ bf16 g_Vh[BHv*Tv*HDv], g_Vl[BHv*Tv*HDv];
__device__ bf16 g_Vth[BHv*HDv*Tv], g_Vtl[BHv*HDv*Tv]; // [bh][hd][t]
__device__ bf16 g_Oh[Bv*Lv*Dv], g_Ol[Bv*Lv*Dv];     // [b*l][D]

// ---------------- helpers ----------------
__device__ __forceinline__ uint32_t smem_u32(const void* p){
    uint32_t a; asm("{ .reg .u64 t; cvta.to.shared.u64 t, %1; cvt.u32.u64 %0, t; }":"=r"(a):"l"(p)); return a;
}
__device__ __forceinline__ void cp16(uint32_t dst, const void* src){
    asm volatile("cp.async.cg.shared.global [%0], [%1], 16;" :: "r"(dst), "l"(src));
}
#define CP_COMMIT() asm volatile("cp.async.commit_group;")
#define CP_WAIT1()  asm volatile("cp.async.wait_group 1;")
#define CP_WAIT0()  asm volatile("cp.async.wait_group 0;")

__device__ __forceinline__ void bsplit(float x, unsigned short &h, unsigned short &l){
    bf16 hb = __float2bfloat16_rn(x);
    bf16 lb = __float2bfloat16_rn(x - __bfloat162float(hb));
    h = __bfloat16_as_ushort(hb); l = __bfloat16_as_ushort(lb);
}
__device__ __forceinline__ void pksplit(float a, float b, unsigned &hi, unsigned &lo){
    unsigned short h0,l0,h1,l1; bsplit(a,h0,l0); bsplit(b,h1,l1);
    hi = (unsigned)h0 | ((unsigned)h1<<16); lo = (unsigned)l0 | ((unsigned)l1<<16);
}
__device__ __forceinline__ void mma_bf16(float c[4], const unsigned a[4], const unsigned b[2]){
    asm volatile("mma.sync.aligned.m16n8k16.row.col.f32.bf16.bf16.f32 "
        "{%0,%1,%2,%3}, {%4,%5,%6,%7}, {%8,%9}, {%0,%1,%2,%3};"
        : "+f"(c[0]), "+f"(c[1]), "+f"(c[2]), "+f"(c[3])
        : "r"(a[0]), "r"(a[1]), "r"(a[2]), "r"(a[3]), "r"(b[0]), "r"(b[1]));
}

// ---------------- prep kernels ----------------
__global__ void fsplit(const float* __restrict__ in, bf16* __restrict__ h, bf16* __restrict__ l, int n){
    int i = blockIdx.x*256 + threadIdx.x;
    if (i < n){ unsigned short a,b; bsplit(in[i],a,b); h[i]=__ushort_as_bfloat16(a); l[i]=__ushort_as_bfloat16(b); }
}
__global__ void wprep(const float* __restrict__ W, bf16* __restrict__ th, bf16* __restrict__ tl, int N){
    __shared__ float t[32][33];
    int k0 = blockIdx.y*32, n0 = blockIdx.x*32, tx = threadIdx.x, ty = threadIdx.y;
    #pragma unroll
    for (int j=0;j<4;j++) t[ty+j*8][tx] = W[(size_t)(k0+ty+j*8)*N + n0+tx];
    __syncthreads();
    #pragma unroll
    for (int j=0;j<4;j++){
        unsigned short h,l; bsplit(t[tx][ty+j*8], h, l);
        size_t o = (size_t)(n0+ty+j*8)*Dv + k0+tx;
        th[o]=__ushort_as_bfloat16(h); tl[o]=__ushort_as_bfloat16(l);
    }
}
__global__ void vtrans(){
    __shared__ bf16 t[32][33];
    int bh = blockIdx.z, t0 = blockIdx.x*32, hd0 = blockIdx.y*32, tx = threadIdx.x, ty = threadIdx.y;
    for (int plane=0; plane<2; plane++){
        const bf16* src = plane ? g_Vl : g_Vh;
        bf16* dst = plane ? g_Vtl : g_Vth;
        #pragma unroll
        for (int j=0;j<4;j++) t[ty+j*8][tx] = src[((size_t)bh*Tv + t0+ty+j*8)*HDv + hd0+tx];
        __syncthreads();
        #pragma unroll
        for (int j=0;j<4;j++) dst[((size_t)bh*HDv + hd0+ty+j*8)*Tv + t0+tx] = t[tx][ty+j*8];
        __syncthreads();
    }
}

// ---------------- HMMA GEMM, cp.async 2-stage ----------------
#define GLD 40
#define G_STG (4*128*GLD)   // elems per stage: Ah,Al,Bh,Bl planes
#define G_SMEM (2*G_STG*2)  // bytes

__global__ __launch_bounds__(256,1) void hgemm(
    const bf16* __restrict__ Agh, const bf16* __restrict__ Agl,
    const bf16* __restrict__ Wgh, const bf16* __restrict__ Wgl,
    const float* __restrict__ bias, int mode, float* __restrict__ outf)
{
    extern __shared__ bf16 gsm[];
    const uint32_t sbase = smem_u32(gsm);
    const int tid = threadIdx.x, lane = tid&31, warp = tid>>5;
    const int g = lane>>2, tig = lane&3;
    const int wm = warp>>2, wn = warp&3;
    const int m0 = blockIdx.y*128, n0 = blockIdx.x*128;

    float acc[4][4][4] = {};

    // issue chunk k0 into stage buf
    auto issue = [&](int buf, int k0){
        #pragma unroll
        for (int t=0;t<8;t++){
            int i = tid + t*256, plane = i>>9, w = i&511, row = w>>2, c4 = (w&3)*8;
            const bf16* src = plane==0?Agh : plane==1?Agl : plane==2?Wgh : Wgl;
            int grow = (plane<2?m0:n0) + row;
            cp16(sbase + (uint32_t)(buf*G_STG + plane*(128*GLD) + row*GLD + c4)*2,
                 src + (size_t)grow*1024 + k0 + c4);
        }
        CP_COMMIT();
    };

    issue(0, 0);
    for (int kb=0; kb<32; kb++){
        if (kb < 31) issue((kb+1)&1, (kb+1)*32);
        if (kb < 31) CP_WAIT1(); else CP_WAIT0();
        __syncthreads();
        const bf16* smA = gsm + (kb&1)*G_STG;
        const bf16* smB = smA + 2*128*GLD;
        #pragma unroll
        for (int ks=0; ks<2; ks++){
            const int kofs = ks*16 + 2*tig;
            unsigned ah[4][4], al[4][4], bh[4][2], bl[4][2];
            #pragma unroll
            for (int mt=0;mt<4;mt++){
                int r = wm*64 + mt*16 + g;
                ah[mt][0] = *(const unsigned*)(smA + r*GLD + kofs);
                ah[mt][1] = *(const unsigned*)(smA + (r+8)*GLD + kofs);
                ah[mt][2] = *(const unsigned*)(smA + r*GLD + kofs + 8);
                ah[mt][3] = *(const unsigned*)(smA + (r+8)*GLD + kofs + 8);
                al[mt][0] = *(const unsigned*)(smA + 128*GLD + r*GLD + kofs);
                al[mt][1] = *(const unsigned*)(smA + 128*GLD + (r+8)*GLD + kofs);
                al[mt][2] = *(const unsigned*)(smA + 128*GLD + r*GLD + kofs + 8);
                al[mt][3] = *(const unsigned*)(smA + 128*GLD + (r+8)*GLD + kofs + 8);
            }
            #pragma unroll
            for (int nt=0;nt<4;nt++){
                int r = wn*32 + nt*8 + g;
                bh[nt][0] = *(const unsigned*)(smB + r*GLD + kofs);
                bh[nt][1] = *(const unsigned*)(smB + r*GLD + kofs + 8);
                bl[nt][0] = *(const unsigned*)(smB + 128*GLD + r*GLD + kofs);
                bl[nt][1] = *(const unsigned*)(smB + 128*GLD + r*GLD + kofs + 8);
            }
            #pragma unroll
            for (int mt=0;mt<4;mt++)
                #pragma unroll
                for (int nt=0;nt<4;nt++){
                    mma_bf16(acc[mt][nt], ah[mt], bh[nt]);
                    mma_bf16(acc[mt][nt], ah[mt], bl[nt]);
                    mma_bf16(acc[mt][nt], al[mt], bh[nt]);
                }
        }
        __syncthreads();
    }

    // epilogue
    #pragma unroll
    for (int mt=0;mt<4;mt++){
        #pragma unroll
        for (int nt=0;nt<4;nt++){
            int r = m0 + wm*64 + mt*16 + g;
            int c = n0 + wn*32 + nt*8 + 2*tig;
            float v00 = acc[mt][nt][0] + bias[c];
            float v01 = acc[mt][nt][1] + bias[c+1];
            float v10 = acc[mt][nt][2] + bias[c];
            float v11 = acc[mt][nt][3] + bias[c+1];
            if (mode == 0){
                *(float2*)(outf + (size_t)r*1024 + c)      = make_float2(v00, v01);
                *(float2*)(outf + (size_t)(r+8)*1024 + c)  = make_float2(v10, v11);
            } else {
                int n2 = c, half = 0;
                if (mode == 2 && c >= 1024){ n2 = c - 1024; half = 1; }
                int h = n2>>6, hd = n2&63;
                bf16 *ph, *pl2;
                if (mode == 1){ ph = g_Qh; pl2 = g_Ql; }
                else if (!half){ ph = g_Kh; pl2 = g_Kl; }
                else { ph = g_Vh; pl2 = g_Vl; }
                float sc = (mode==1) ? 0.125f : 1.0f;
                #pragma unroll
                for (int rr=0; rr<2; rr++){
                    int m = r + rr*8;
                    int b = m>>11, l = m&2047;
                    size_t base = ((size_t)(b*16 + h)*2048 + l)*64 + hd;
                    unsigned hi, lo;
                    pksplit((rr?v10:v00)*sc, (rr?v11:v01)*sc, hi, lo);
                    *(unsigned*)(ph  + base) = hi;
                    *(unsigned*)(pl2 + base) = lo;
                }
            }
        }
    }
}

// ---------------- HMMA flash attention, cp.async 2-stage ----------------
#define ALD 72
#define QH_O 0
#define QL_O (64*ALD)
#define STG0 (2*64*ALD)
#define A_STG (4*64*ALD)            // per-stage elems: Kh,Kl,Vh,Vl planes
#define SM_ELEMS (STG0 + 2*A_STG)   // 46080 bf16
#define ATT_SMEM (SM_ELEMS*2 + 2*64*4)

__global__ __launch_bounds__(128) void hattn(const int* __restrict__ mask)
{
    extern __shared__ bf16 sm[];
    const uint32_t sbase = smem_u32(sm);
    float* mflag = (float*)(sm + SM_ELEMS);   // [2][64]
    const int tid = threadIdx.x, lane = tid&31, warp = tid>>5;
    const int g = lane>>2, tig = lane&3;
    const int bh = blockIdx.y, b = bh>>4, h = bh&15, l0 = blockIdx.x*64;
    const int* mg = mask + b*Tv;

    auto issueKV = [&](int buf, int t0){
        #pragma unroll
        for (int t=0;t<16;t++){
            int i = tid + t*128, plane = i>>9, w = i&511, row = w>>3, c8 = (w&7)*8;
            const bf16* gp;
            if (plane == 0)      gp = g_Kh  + ((size_t)bh*Tv + t0 + row)*64 + c8;
            else if (plane == 1) gp = g_Kl  + ((size_t)bh*Tv + t0 + row)*64 + c8;
            else if (plane == 2) gp = g_Vth + ((size_t)bh*HDv + row)*Tv + t0 + c8;
            else                 gp = g_Vtl + ((size_t)bh*HDv + row)*Tv + t0 + c8;
            cp16(sbase + (uint32_t)(STG0 + buf*A_STG + plane*(64*ALD) + row*ALD + c8)*2, gp);
        }
        CP_COMMIT();
    };

    // Q planes -> smem; preload KV stage 0; mask chunk 0
    #pragma unroll
    for (int t=0;t<8;t++){
        int i = tid + t*128, plane = i>>9, w = i&511, row = w>>3, c8 = (w&7)*8;
        const bf16* src = plane ? g_Ql : g_Qh;
        uint4 v = *(const uint4*)(src + ((size_t)bh*Lv + l0 + row)*64 + c8);
        *(uint4*)(sm + (plane?QL_O:QH_O) + row*ALD + c8) = v;
    }
    issueKV(0, 0);
    if (tid < 64) mflag[tid] = (mg[tid] != 0) ? 1.f : 0.f;
    __syncthreads();

    // preload Q fragments (resident)
    unsigned qa[4][2][4];
    {
        int r = warp*16 + g;
        #pragma unroll
        for (int kk=0; kk<4; kk++){
            int kofs = kk*16 + 2*tig;
            #pragma unroll
            for (int p=0; p<2; p++){
                const bf16* q = sm + (p?QL_O:QH_O);
                qa[kk][p][0] = *(const unsigned*)(q + r*ALD + kofs);
                qa[kk][p][1] = *(const unsigned*)(q + (r+8)*ALD + kofs);
                qa[kk][p][2] = *(const unsigned*)(q + r*ALD + kofs + 8);
                qa[kk][p][3] = *(const unsigned*)(q + (r+8)*ALD + kofs + 8);
            }
        }
    }

    float mold[2] = {-INFINITY, -INFINITY};
    float lsum[2] = {0.f, 0.f};
    float o[8][4] = {};

    for (int ci=0; ci<32; ci++){
        const int t0 = ci*64;
        if (ci < 31) issueKV((ci+1)&1, t0+64);
        float mnext = 0.f;
        if (tid < 64 && ci < 31) mnext = (mg[t0+64+tid] != 0) ? 1.f : 0.f;
        if (ci < 31) CP_WAIT1(); else CP_WAIT0();
        __syncthreads();

        const bf16* KH = sm + STG0 + (ci&1)*A_STG;
        const bf16* KL = KH + 64*ALD;
        const bf16* VH = KH + 2*64*ALD;
        const bf16* VL = KH + 3*64*ALD;
        const float* mf = mflag + (ci&1)*64;

        // S = Q K^T  (QhKh + QhKl + QlKh)
        float s[8][4] = {};
        #pragma unroll
        for (int kk=0; kk<4; kk++){
            int kofs = kk*16 + 2*tig;
            unsigned bhf[8][2], blf[8][2];
            #pragma unroll
            for (int nt=0; nt<8; nt++){
                int r = nt*8 + g;
                bhf[nt][0] = *(const unsigned*)(KH + r*ALD + kofs);
                bhf[nt][1] = *(const unsigned*)(KH + r*ALD + kofs + 8);
                blf[nt][0] = *(const unsigned*)(KL + r*ALD + kofs);
                blf[nt][1] = *(const unsigned*)(KL + r*ALD + kofs + 8);
            }
            #pragma unroll
            for (int nt=0; nt<8; nt++){
                mma_bf16(s[nt], qa[kk][0], bhf[nt]);
                mma_bf16(s[nt], qa[kk][0], blf[nt]);
                mma_bf16(s[nt], qa[kk][1], bhf[nt]);
            }
        }

        // mask + online softmax (rows g, g+8)
        float ma = mold[0], mb = mold[1];
        #pragma unroll
        for (int nt=0; nt<8; nt++){
            int c = nt*8 + 2*tig;
            if (mf[c]   == 0.f){ s[nt][0] = -1e9f; s[nt][2] = -1e9f; }
            if (mf[c+1] == 0.f){ s[nt][1] = -1e9f; s[nt][3] = -1e9f; }
            ma = fmaxf(ma, fmaxf(s[nt][0], s[nt][1]));
            mb = fmaxf(mb, fmaxf(s[nt][2], s[nt][3]));
        }
        ma = fmaxf(ma, __shfl_xor_sync(0xffffffffu, ma, 1));
        ma = fmaxf(ma, __shfl_xor_sync(0xffffffffu, ma, 2));
        mb = fmaxf(mb, __shfl_xor_sync(0xffffffffu, mb, 1));
        mb = fmaxf(mb, __shfl_xor_sync(0xffffffffu, mb, 2));

        float aa = __expf(mold[0] - ma), ab = __expf(mold[1] - mb);
        float suma = 0.f, sumb = 0.f;
        #pragma unroll
        for (int nt=0; nt<8; nt++){
            s[nt][0] = __expf(s[nt][0] - ma);
            s[nt][1] = __expf(s[nt][1] - ma);
            s[nt][2] = __expf(s[nt][2] - mb);
            s[nt][3] = __expf(s[nt][3] - mb);
            suma += s[nt][0] + s[nt][1];
            sumb += s[nt][2] + s[nt][3];
        }
        suma += __shfl_xor_sync(0xffffffffu, suma, 1);
        suma += __shfl_xor_sync(0xffffffffu, suma, 2);
        sumb += __shfl_xor_sync(0xffffffffu, sumb, 1);
        sumb += __shfl_xor_sync(0xffffffffu, sumb, 2);
        lsum[0] = lsum[0]*aa + suma;  mold[0] = ma;
        lsum[1] = lsum[1]*ab + sumb;  mold[1] = mb;
        #pragma unroll
        for (int nt=0; nt<8; nt++){
            o[nt][0] *= aa; o[nt][1] *= aa; o[nt][2] *= ab; o[nt][3] *= ab;
        }

        // PV (PhVh + PhVl + PlVh)
        #pragma unroll
        for (int kt=0; kt<4; kt++){
            unsigned pah[4], pal[4];
            pksplit(s[2*kt][0],   s[2*kt][1],   pah[0], pal[0]);
            pksplit(s[2*kt][2],   s[2*kt][3],   pah[1], pal[1]);
            pksplit(s[2*kt+1][0], s[2*kt+1][1], pah[2], pal[2]);
            pksplit(s[2*kt+1][2], s[2*kt+1][3], pah[3], pal[3]);
            int kofs = kt*16 + 2*tig;
            #pragma unroll
            for (int nt=0; nt<8; nt++){
                int r = nt*8 + g;
                unsigned vh[2], vl[2];
                vh[0] = *(const unsigned*)(VH + r*ALD + kofs);
                vh[1] = *(const unsigned*)(VH + r*ALD + kofs + 8);
                vl[0] = *(const unsigned*)(VL + r*ALD + kofs);
                vl[1] = *(const unsigned*)(VL + r*ALD + kofs + 8);
                mma_bf16(o[nt], pah, vh);
                mma_bf16(o[nt], pah, vl);
                mma_bf16(o[nt], pal, vh);
            }
        }
        if (tid < 64 && ci < 31) mflag[((ci+1)&1)*64 + tid] = mnext;
        __syncthreads();
    }

    // normalize + write split O planes
    float inva = 1.0f / lsum[0], invb = 1.0f / lsum[1];
    int ra = l0 + warp*16 + g, rb = ra + 8;
    #pragma unroll
    for (int nt=0; nt<8; nt++){
        int c = h*64 + nt*8 + 2*tig;
        unsigned hi, lo;
        size_t basea = ((size_t)(b*Lv + ra))*Dv + c;
        pksplit(o[nt][0]*inva, o[nt][1]*inva, hi, lo);
        *(unsigned*)(g_Oh + basea) = hi;
        *(unsigned*)(g_Ol + basea) = lo;
        size_t baseb = ((size_t)(b*Lv + rb))*Dv + c;
        pksplit(o[nt][2]*invb, o[nt][3]*invb, hi, lo);
        *(unsigned*)(g_Oh + baseb) = hi;
        *(unsigned*)(g_Ol + baseb) = lo;
    }
}

// ---------------- launch ----------------
extern "C" void kernel_launch(void* const* d_in, const int* in_sizes, int n_in,
                              void* d_out, int out_size)
{
    const float* x     = (const float*)d_in[0];
    const float* ctx   = (const float*)d_in[1];
    const int*   cmsk  = (const int*)d_in[2];
    const float* Wq    = (const float*)d_in[3];
    const float* bq    = (const float*)d_in[4];
    const float* Wkv   = (const float*)d_in[5];
    const float* bkv   = (const float*)d_in[6];
    const float* Wproj = (const float*)d_in[7];
    const float* bproj = (const float*)d_in[8];
    float* out         = (float*)d_out;

    bf16 *xh,*xl,*ch,*cl,*wqh,*wql,*wkh,*wkl,*wph,*wpl,*oh,*ol;
    cudaGetSymbolAddress((void**)&xh, g_xh);   cudaGetSymbolAddress((void**)&xl, g_xl);
    cudaGetSymbolAddress((void**)&ch, g_ch);   cudaGetSymbolAddress((void**)&cl, g_cl);
    cudaGetSymbolAddress((void**)&wqh, g_Wqh); cudaGetSymbolAddress((void**)&wql, g_Wql);
    cudaGetSymbolAddress((void**)&wkh, g_Wkh); cudaGetSymbolAddress((void**)&wkl, g_Wkl);
    cudaGetSymbolAddress((void**)&wph, g_Wph); cudaGetSymbolAddress((void**)&wpl, g_Wpl);
    cudaGetSymbolAddress((void**)&oh, g_Oh);   cudaGetSymbolAddress((void**)&ol, g_Ol);

    cudaFuncSetAttribute(hgemm, cudaFuncAttributeMaxDynamicSharedMemorySize, G_SMEM);
    cudaFuncSetAttribute(hattn, cudaFuncAttributeMaxDynamicSharedMemorySize, ATT_SMEM);

    const int NM = Bv*Lv;  // 4096

    fsplit<<<NM*Dv/256, 256>>>(x, xh, xl, NM*Dv);
    fsplit<<<NM*Dv/256, 256>>>(ctx, ch, cl, NM*Dv);
    wprep<<<dim3(Dv/32, Dv/32), dim3(32,8)>>>(Wq, wqh, wql, Dv);
    wprep<<<dim3(2*Dv/32, Dv/32), dim3(32,8)>>>(Wkv, wkh, wkl, 2*Dv);
    wprep<<<dim3(Dv/32, Dv/32), dim3(32,8)>>>(Wproj, wph, wpl, Dv);

    hgemm<<<dim3(Dv/128, NM/128), 256, G_SMEM>>>(xh, xl, wqh, wql, bq, 1, nullptr);
    hgemm<<<dim3(2*Dv/128, NM/128), 256, G_SMEM>>>(ch, cl, wkh, wkl, bkv, 2, nullptr);
    vtrans<<<dim3(Tv/32, HDv/32, BHv), dim3(32,8)>>>();
    hattn<<<dim3(Lv/64, BHv), 128, ATT_SMEM>>>(cmsk);
    hgemm<<<dim3(Dv/128, NM/128), 256, G_SMEM>>>(oh, ol, wph, wpl, bproj, 0, out);
}

// round 7
// speedup vs baseline: 3.3462x; 1.0886x over previous
#include <cuda_runtime.h>
#include <cuda_bf16.h>
#include <math.h>
#include <stdint.h>

#define Bv 2
#define Lv 2048
#define Tv 2048
#define Dv 1024
#define Hv 16
#define HDv 64
#define BHv (Bv*Hv)
typedef __nv_bfloat16 bf16;

// ---------------- scratch ----------------
__device__ bf16 g_xh[Bv*Lv*Dv], g_xl[Bv*Lv*Dv];
__device__ bf16 g_ch[Bv*Tv*Dv], g_cl[Bv*Tv*Dv];
__device__ bf16 g_Wqh[Dv*Dv],   g_Wql[Dv*Dv];        // [N][K]
__device__ bf16 g_Wkh[2*Dv*Dv], g_Wkl[2*Dv*Dv];
__device__ bf16 g_Wph[Dv*Dv],   g_Wpl[Dv*Dv];
__device__ bf16 g_Qh[BHv*Lv*HDv], g_Ql[BHv*Lv*HDv]; // [bh][l][hd] (scaled 0.125)
__device__ bf16 g_Kh[BHv*Tv*HDv], g_Kl[BHv*Tv*HDv];
__device__ bf16 g_Vh[BHv*Tv*HDv], g_Vl[BHv*Tv*HDv];
__device__ bf16 g_Vth[BHv*HDv*Tv], g_Vtl[BHv*HDv*Tv]; // [bh][hd][t]
__device__ bf16 g_Oh[Bv*Lv*Dv], g_Ol[Bv*Lv*Dv];     // [b*l][D]

// ---------------- helpers ----------------
__device__ __forceinline__ uint32_t smem_u32(const void* p){
    uint32_t a; asm("{ .reg .u64 t; cvta.to.shared.u64 t, %1; cvt.u32.u64 %0, t; }":"=r"(a):"l"(p)); return a;
}
__device__ __forceinline__ void cp16(uint32_t dst, const void* src){
    asm volatile("cp.async.cg.shared.global [%0], [%1], 16;" :: "r"(dst), "l"(src));
}
#define CP_COMMIT() asm volatile("cp.async.commit_group;")
#define CP_WAIT1()  asm volatile("cp.async.wait_group 1;")
#define CP_WAIT0()  asm volatile("cp.async.wait_group 0;")

__device__ __forceinline__ void ldsm4(unsigned r[4], uint32_t a){
    asm volatile("ldmatrix.sync.aligned.m8n8.x4.shared.b16 {%0,%1,%2,%3}, [%4];"
        : "=r"(r[0]), "=r"(r[1]), "=r"(r[2]), "=r"(r[3]) : "r"(a));
}
__device__ __forceinline__ void bsplit(float x, unsigned short &h, unsigned short &l){
    bf16 hb = __float2bfloat16_rn(x);
    bf16 lb = __float2bfloat16_rn(x - __bfloat162float(hb));
    h = __bfloat16_as_ushort(hb); l = __bfloat16_as_ushort(lb);
}
__device__ __forceinline__ void pksplit(float a, float b, unsigned &hi, unsigned &lo){
    unsigned short h0,l0,h1,l1; bsplit(a,h0,l0); bsplit(b,h1,l1);
    hi = (unsigned)h0 | ((unsigned)h1<<16); lo = (unsigned)l0 | ((unsigned)l1<<16);
}
__device__ __forceinline__ void mma_bf16(float c[4], const unsigned a[4], const unsigned b[2]){
    asm volatile("mma.sync.aligned.m16n8k16.row.col.f32.bf16.bf16.f32 "
        "{%0,%1,%2,%3}, {%4,%5,%6,%7}, {%8,%9}, {%0,%1,%2,%3};"
        : "+f"(c[0]), "+f"(c[1]), "+f"(c[2]), "+f"(c[3])
        : "r"(a[0]), "r"(a[1]), "r"(a[2]), "r"(a[3]), "r"(b[0]), "r"(b[1]));
}

// ---------------- prep kernels ----------------
__global__ void fsplit(const float* __restrict__ in, bf16* __restrict__ h, bf16* __restrict__ l, int n){
    int i = blockIdx.x*256 + threadIdx.x;
    if (i < n){ unsigned short a,b; bsplit(in[i],a,b); h[i]=__ushort_as_bfloat16(a); l[i]=__ushort_as_bfloat16(b); }
}
__global__ void wprep(const float* __restrict__ W, bf16* __restrict__ th, bf16* __restrict__ tl, int N){
    __shared__ float t[32][33];
    int k0 = blockIdx.y*32, n0 = blockIdx.x*32, tx = threadIdx.x, ty = threadIdx.y;
    #pragma unroll
    for (int j=0;j<4;j++) t[ty+j*8][tx] = W[(size_t)(k0+ty+j*8)*N + n0+tx];
    __syncthreads();
    #pragma unroll
    for (int j=0;j<4;j++){
        unsigned short h,l; bsplit(t[tx][ty+j*8], h, l);
        size_t o = (size_t)(n0+ty+j*8)*Dv + k0+tx;
        th[o]=__ushort_as_bfloat16(h); tl[o]=__ushort_as_bfloat16(l);
    }
}
__global__ void vtrans(){
    __shared__ bf16 t[32][33];
    int bh = blockIdx.z, t0 = blockIdx.x*32, hd0 = blockIdx.y*32, tx = threadIdx.x, ty = threadIdx.y;
    for (int plane=0; plane<2; plane++){
        const bf16* src = plane ? g_Vl : g_Vh;
        bf16* dst = plane ? g_Vtl : g_Vth;
        #pragma unroll
        for (int j=0;j<4;j++) t[ty+j*8][tx] = src[((size_t)bh*Tv + t0+ty+j*8)*HDv + hd0+tx];
        __syncthreads();
        #pragma unroll
        for (int j=0;j<4;j++) dst[((size_t)bh*HDv + hd0+ty+j*8)*Tv + t0+tx] = t[tx][ty+j*8];
        __syncthreads();
    }
}

// ---------------- HMMA GEMM, cp.async 2-stage + ldmatrix ----------------
#define GLD 40
#define G_STG (4*128*GLD)   // elems per stage: Ah,Al,Bh,Bl planes
#define G_SMEM (2*G_STG*2)  // bytes

__global__ __launch_bounds__(256,2) void hgemm(
    const bf16* __restrict__ Agh, const bf16* __restrict__ Agl,
    const bf16* __restrict__ Wgh, const bf16* __restrict__ Wgl,
    const float* __restrict__ bias, int mode, float* __restrict__ outf)
{
    extern __shared__ bf16 gsm[];
    const uint32_t sbase = smem_u32(gsm);
    const int tid = threadIdx.x, lane = tid&31, warp = tid>>5;
    const int g = lane>>2, tig = lane&3;
    const int wm = warp>>2, wn = warp&3;
    const int m0 = blockIdx.y*128, n0 = blockIdx.x*128;
    // ldmatrix per-lane tile decomposition
    const int lrow = lane&7, ltile = lane>>3;
    const int rowA = (ltile&1)*8 + lrow, kA = (ltile>>1)*8;   // A: tiles (r0-7,klo)(r8-15,klo)(r0-7,khi)(r8-15,khi)
    const int rowB = (ltile>>1)*8 + lrow, kB = (ltile&1)*8;   // B: tiles (n0-7,klo)(n0-7,khi)(n8-15,klo)(n8-15,khi)

    float acc[4][4][4] = {};

    auto issue = [&](int buf, int k0){
        #pragma unroll
        for (int t=0;t<8;t++){
            int i = tid + t*256, plane = i>>9, w = i&511, row = w>>2, c4 = (w&3)*8;
            const bf16* src = plane==0?Agh : plane==1?Agl : plane==2?Wgh : Wgl;
            int grow = (plane<2?m0:n0) + row;
            cp16(sbase + (uint32_t)(buf*G_STG + plane*(128*GLD) + row*GLD + c4)*2,
                 src + (size_t)grow*1024 + k0 + c4);
        }
        CP_COMMIT();
    };

    issue(0, 0);
    for (int kb=0; kb<32; kb++){
        if (kb < 31) issue((kb+1)&1, (kb+1)*32);
        if (kb < 31) CP_WAIT1(); else CP_WAIT0();
        __syncthreads();
        const uint32_t aB = sbase + (uint32_t)((kb&1)*G_STG)*2;
        const uint32_t bB = aB + 2*128*GLD*2;
        #pragma unroll
        for (int ks=0; ks<2; ks++){
            unsigned ah[4][4], al[4][4], bh[4][2], bl[4][2];
            #pragma unroll
            for (int mt=0;mt<4;mt++){
                uint32_t off = (uint32_t)((wm*64 + mt*16 + rowA)*GLD + ks*16 + kA)*2;
                ldsm4(ah[mt], aB + off);
                ldsm4(al[mt], aB + 128*GLD*2 + off);
            }
            #pragma unroll
            for (int p2=0;p2<2;p2++){
                unsigned r4[4];
                uint32_t off = (uint32_t)((wn*32 + p2*16 + rowB)*GLD + ks*16 + kB)*2;
                ldsm4(r4, bB + off);
                bh[2*p2][0]=r4[0]; bh[2*p2][1]=r4[1]; bh[2*p2+1][0]=r4[2]; bh[2*p2+1][1]=r4[3];
                ldsm4(r4, bB + 128*GLD*2 + off);
                bl[2*p2][0]=r4[0]; bl[2*p2][1]=r4[1]; bl[2*p2+1][0]=r4[2]; bl[2*p2+1][1]=r4[3];
            }
            #pragma unroll
            for (int mt=0;mt<4;mt++)
                #pragma unroll
                for (int nt=0;nt<4;nt++){
                    mma_bf16(acc[mt][nt], ah[mt], bh[nt]);
                    mma_bf16(acc[mt][nt], ah[mt], bl[nt]);
                    mma_bf16(acc[mt][nt], al[mt], bh[nt]);
                }
        }
        __syncthreads();
    }

    // epilogue
    #pragma unroll
    for (int mt=0;mt<4;mt++){
        #pragma unroll
        for (int nt=0;nt<4;nt++){
            int r = m0 + wm*64 + mt*16 + g;
            int c = n0 + wn*32 + nt*8 + 2*tig;
            float v00 = acc[mt][nt][0] + bias[c];
            float v01 = acc[mt][nt][1] + bias[c+1];
            float v10 = acc[mt][nt][2] + bias[c];
            float v11 = acc[mt][nt][3] + bias[c+1];
            if (mode == 0){
                *(float2*)(outf + (size_t)r*1024 + c)      = make_float2(v00, v01);
                *(float2*)(outf + (size_t)(r+8)*1024 + c)  = make_float2(v10, v11);
            } else {
                int n2 = c, half = 0;
                if (mode == 2 && c >= 1024){ n2 = c - 1024; half = 1; }
                int h = n2>>6, hd = n2&63;
                bf16 *ph, *pl2;
                if (mode == 1){ ph = g_Qh; pl2 = g_Ql; }
                else if (!half){ ph = g_Kh; pl2 = g_Kl; }
                else { ph = g_Vh; pl2 = g_Vl; }
                float sc = (mode==1) ? 0.125f : 1.0f;
                #pragma unroll
                for (int rr=0; rr<2; rr++){
                    int m = r + rr*8;
                    int b = m>>11, l = m&2047;
                    size_t base = ((size_t)(b*16 + h)*2048 + l)*64 + hd;
                    unsigned hi, lo;
                    pksplit((rr?v10:v00)*sc, (rr?v11:v01)*sc, hi, lo);
                    *(unsigned*)(ph  + base) = hi;
                    *(unsigned*)(pl2 + base) = lo;
                }
            }
        }
    }
}

// ---------------- HMMA flash attention, cp.async 2-stage + ldmatrix ----------------
#define ALD 72
#define QH_O 0
#define QL_O (64*ALD)
#define STG0 (2*64*ALD)
#define A_STG (4*64*ALD)            // per-stage elems: Kh,Kl,Vh,Vl planes
#define SM_ELEMS (STG0 + 2*A_STG)   // 46080 bf16
#define ATT_SMEM (SM_ELEMS*2 + 2*64*4)

__global__ __launch_bounds__(128) void hattn(const int* __restrict__ mask)
{
    extern __shared__ bf16 sm[];
    const uint32_t sbase = smem_u32(sm);
    float* mflag = (float*)(sm + SM_ELEMS);   // [2][64]
    const int tid = threadIdx.x, lane = tid&31, warp = tid>>5;
    const int g = lane>>2, tig = lane&3;
    const int bh = blockIdx.y, b = bh>>4, h = bh&15, l0 = blockIdx.x*64;
    const int* mg = mask + b*Tv;
    const int lrow = lane&7, ltile = lane>>3;
    const int rowA = (ltile&1)*8 + lrow, kA = (ltile>>1)*8;
    const int rowB = (ltile>>1)*8 + lrow, kB = (ltile&1)*8;

    auto issueKV = [&](int buf, int t0){
        #pragma unroll
        for (int t=0;t<16;t++){
            int i = tid + t*128, plane = i>>9, w = i&511, row = w>>3, c8 = (w&7)*8;
            const bf16* gp;
            if (plane == 0)      gp = g_Kh  + ((size_t)bh*Tv + t0 + row)*64 + c8;
            else if (plane == 1) gp = g_Kl  + ((size_t)bh*Tv + t0 + row)*64 + c8;
            else if (plane == 2) gp = g_Vth + ((size_t)bh*HDv + row)*Tv + t0 + c8;
            else                 gp = g_Vtl + ((size_t)bh*HDv + row)*Tv + t0 + c8;
            cp16(sbase + (uint32_t)(STG0 + buf*A_STG + plane*(64*ALD) + row*ALD + c8)*2, gp);
        }
        CP_COMMIT();
    };

    // Q planes -> smem; preload KV stage 0; mask chunk 0
    #pragma unroll
    for (int t=0;t<8;t++){
        int i = tid + t*128, plane = i>>9, w = i&511, row = w>>3, c8 = (w&7)*8;
        const bf16* src = plane ? g_Ql : g_Qh;
        uint4 v = *(const uint4*)(src + ((size_t)bh*Lv + l0 + row)*64 + c8);
        *(uint4*)(sm + (plane?QL_O:QH_O) + row*ALD + c8) = v;
    }
    issueKV(0, 0);
    if (tid < 64) mflag[tid] = (mg[tid] != 0) ? 1.f : 0.f;
    __syncthreads();

    // preload Q fragments via ldmatrix (resident)
    unsigned qa[4][2][4];
    #pragma unroll
    for (int kk=0; kk<4; kk++)
        #pragma unroll
        for (int p=0; p<2; p++)
            ldsm4(qa[kk][p], sbase + (uint32_t)((p?QL_O:QH_O) + (warp*16 + rowA)*ALD + kk*16 + kA)*2);

    float mold[2] = {-INFINITY, -INFINITY};
    float lsum[2] = {0.f, 0.f};
    float o[8][4] = {};

    for (int ci=0; ci<32; ci++){
        const int t0 = ci*64;
        if (ci < 31) issueKV((ci+1)&1, t0+64);
        float mnext = 0.f;
        if (tid < 64 && ci < 31) mnext = (mg[t0+64+tid] != 0) ? 1.f : 0.f;
        if (ci < 31) CP_WAIT1(); else CP_WAIT0();
        __syncthreads();

        const uint32_t khB = sbase + (uint32_t)(STG0 + (ci&1)*A_STG)*2;
        const uint32_t klB = khB + 64*ALD*2;
        const uint32_t vhB = khB + 2*64*ALD*2;
        const uint32_t vlB = khB + 3*64*ALD*2;
        const float* mf = mflag + (ci&1)*64;

        // S = Q K^T  (QhKh + QhKl + QlKh)
        float s[8][4] = {};
        #pragma unroll
        for (int kk=0; kk<4; kk++){
            unsigned bhf[8][2], blf[8][2];
            #pragma unroll
            for (int p2=0; p2<4; p2++){
                unsigned r4[4];
                uint32_t off = (uint32_t)((p2*16 + rowB)*ALD + kk*16 + kB)*2;
                ldsm4(r4, khB + off);
                bhf[2*p2][0]=r4[0]; bhf[2*p2][1]=r4[1]; bhf[2*p2+1][0]=r4[2]; bhf[2*p2+1][1]=r4[3];
                ldsm4(r4, klB + off);
                blf[2*p2][0]=r4[0]; blf[2*p2][1]=r4[1]; blf[2*p2+1][0]=r4[2]; blf[2*p2+1][1]=r4[3];
            }
            #pragma unroll
            for (int nt=0; nt<8; nt++){
                mma_bf16(s[nt], qa[kk][0], bhf[nt]);
                mma_bf16(s[nt], qa[kk][0], blf[nt]);
                mma_bf16(s[nt], qa[kk][1], bhf[nt]);
            }
        }

        // mask + online softmax (rows g, g+8)
        float ma = mold[0], mb = mold[1];
        #pragma unroll
        for (int nt=0; nt<8; nt++){
            int c = nt*8 + 2*tig;
            if (mf[c]   == 0.f){ s[nt][0] = -1e9f; s[nt][2] = -1e9f; }
            if (mf[c+1] == 0.f){ s[nt][1] = -1e9f; s[nt][3] = -1e9f; }
            ma = fmaxf(ma, fmaxf(s[nt][0], s[nt][1]));
            mb = fmaxf(mb, fmaxf(s[nt][2], s[nt][3]));
        }
        ma = fmaxf(ma, __shfl_xor_sync(0xffffffffu, ma, 1));
        ma = fmaxf(ma, __shfl_xor_sync(0xffffffffu, ma, 2));
        mb = fmaxf(mb, __shfl_xor_sync(0xffffffffu, mb, 1));
        mb = fmaxf(mb, __shfl_xor_sync(0xffffffffu, mb, 2));

        float aa = __expf(mold[0] - ma), ab = __expf(mold[1] - mb);
        float suma = 0.f, sumb = 0.f;
        #pragma unroll
        for (int nt=0; nt<8; nt++){
            s[nt][0] = __expf(s[nt][0] - ma);
            s[nt][1] = __expf(s[nt][1] - ma);
            s[nt][2] = __expf(s[nt][2] - mb);
            s[nt][3] = __expf(s[nt][3] - mb);
            suma += s[nt][0] + s[nt][1];
            sumb += s[nt][2] + s[nt][3];
        }
        suma += __shfl_xor_sync(0xffffffffu, suma, 1);
        suma += __shfl_xor_sync(0xffffffffu, suma, 2);
        sumb += __shfl_xor_sync(0xffffffffu, sumb, 1);
        sumb += __shfl_xor_sync(0xffffffffu, sumb, 2);
        lsum[0] = lsum[0]*aa + suma;  mold[0] = ma;
        lsum[1] = lsum[1]*ab + sumb;  mold[1] = mb;
        #pragma unroll
        for (int nt=0; nt<8; nt++){
            o[nt][0] *= aa; o[nt][1] *= aa; o[nt][2] *= ab; o[nt][3] *= ab;
        }

        // PV (PhVh + PhVl + PlVh)
        #pragma unroll
        for (int kt=0; kt<4; kt++){
            unsigned pah[4], pal[4];
            pksplit(s[2*kt][0],   s[2*kt][1],   pah[0], pal[0]);
            pksplit(s[2*kt][2],   s[2*kt][3],   pah[1], pal[1]);
            pksplit(s[2*kt+1][0], s[2*kt+1][1], pah[2], pal[2]);
            pksplit(s[2*kt+1][2], s[2*kt+1][3], pah[3], pal[3]);
            #pragma unroll
            for (int p2=0; p2<4; p2++){
                unsigned rv[4], rl[4];
                uint32_t off = (uint32_t)((p2*16 + rowB)*ALD + kt*16 + kB)*2;
                ldsm4(rv, vhB + off);
                ldsm4(rl, vlB + off);
                unsigned v0h[2] = {rv[0], rv[1]}, v1h[2] = {rv[2], rv[3]};
                unsigned v0l[2] = {rl[0], rl[1]}, v1l[2] = {rl[2], rl[3]};
                mma_bf16(o[2*p2],   pah, v0h);
                mma_bf16(o[2*p2],   pah, v0l);
                mma_bf16(o[2*p2],   pal, v0h);
                mma_bf16(o[2*p2+1], pah, v1h);
                mma_bf16(o[2*p2+1], pah, v1l);
                mma_bf16(o[2*p2+1], pal, v1h);
            }
        }
        if (tid < 64 && ci < 31) mflag[((ci+1)&1)*64 + tid] = mnext;
        __syncthreads();
    }

    // normalize + write split O planes
    float inva = 1.0f / lsum[0], invb = 1.0f / lsum[1];
    int ra = l0 + warp*16 + g, rb = ra + 8;
    #pragma unroll
    for (int nt=0; nt<8; nt++){
        int c = h*64 + nt*8 + 2*tig;
        unsigned hi, lo;
        size_t basea = ((size_t)(b*Lv + ra))*Dv + c;
        pksplit(o[nt][0]*inva, o[nt][1]*inva, hi, lo);
        *(unsigned*)(g_Oh + basea) = hi;
        *(unsigned*)(g_Ol + basea) = lo;
        size_t baseb = ((size_t)(b*Lv + rb))*Dv + c;
        pksplit(o[nt][2]*invb, o[nt][3]*invb, hi, lo);
        *(unsigned*)(g_Oh + baseb) = hi;
        *(unsigned*)(g_Ol + baseb) = lo;
    }
}

// ---------------- launch ----------------
extern "C" void kernel_launch(void* const* d_in, const int* in_sizes, int n_in,
                              void* d_out, int out_size)
{
    const float* x     = (const float*)d_in[0];
    const float* ctx   = (const float*)d_in[1];
    const int*   cmsk  = (const int*)d_in[2];
    const float* Wq    = (const float*)d_in[3];
    const float* bq    = (const float*)d_in[4];
    const float* Wkv   = (const float*)d_in[5];
    const float* bkv   = (const float*)d_in[6];
    const float* Wproj = (const float*)d_in[7];
    const float* bproj = (const float*)d_in[8];
    float* out         = (float*)d_out;

    bf16 *xh,*xl,*ch,*cl,*wqh,*wql,*wkh,*wkl,*wph,*wpl,*oh,*ol;
    cudaGetSymbolAddress((void**)&xh, g_xh);   cudaGetSymbolAddress((void**)&xl, g_xl);
    cudaGetSymbolAddress((void**)&ch, g_ch);   cudaGetSymbolAddress((void**)&cl, g_cl);
    cudaGetSymbolAddress((void**)&wqh, g_Wqh); cudaGetSymbolAddress((void**)&wql, g_Wql);
    cudaGetSymbolAddress((void**)&wkh, g_Wkh); cudaGetSymbolAddress((void**)&wkl, g_Wkl);
    cudaGetSymbolAddress((void**)&wph, g_Wph); cudaGetSymbolAddress((void**)&wpl, g_Wpl);
    cudaGetSymbolAddress((void**)&oh, g_Oh);   cudaGetSymbolAddress((void**)&ol, g_Ol);

    cudaFuncSetAttribute(hgemm, cudaFuncAttributeMaxDynamicSharedMemorySize, G_SMEM);
    cudaFuncSetAttribute(hattn, cudaFuncAttributeMaxDynamicSharedMemorySize, ATT_SMEM);

    const int NM = Bv*Lv;  // 4096

    fsplit<<<NM*Dv/256, 256>>>(x, xh, xl, NM*Dv);
    fsplit<<<NM*Dv/256, 256>>>(ctx, ch, cl, NM*Dv);
    wprep<<<dim3(Dv/32, Dv/32), dim3(32,8)>>>(Wq, wqh, wql, Dv);
    wprep<<<dim3(2*Dv/32, Dv/32), dim3(32,8)>>>(Wkv, wkh, wkl, 2*Dv);
    wprep<<<dim3(Dv/32, Dv/32), dim3(32,8)>>>(Wproj, wph, wpl, Dv);

    hgemm<<<dim3(Dv/128, NM/128), 256, G_SMEM>>>(xh, xl, wqh, wql, bq, 1, nullptr);
    hgemm<<<dim3(2*Dv/128, NM/128), 256, G_SMEM>>>(ch, cl, wkh, wkl, bkv, 2, nullptr);
    vtrans<<<dim3(Tv/32, HDv/32, BHv), dim3(32,8)>>>();
    hattn<<<dim3(Lv/64, BHv), 128, ATT_SMEM>>>(cmsk);
    hgemm<<<dim3(Dv/128, NM/128), 256, G_SMEM>>>(oh, ol, wph, wpl, bproj, 0, out);
}

// round 8
// speedup vs baseline: 4.3545x; 1.3013x over previous
#include <cuda_runtime.h>
#include <cuda_bf16.h>
#include <math.h>
#include <stdint.h>

#define Bv 2
#define Lv 2048
#define Tv 2048
#define Dv 1024
#define Hv 16
#define HDv 64
#define BHv (Bv*Hv)
typedef __nv_bfloat16 bf16;

// ---------------- scratch ----------------
__device__ bf16 g_xh[Bv*Lv*Dv], g_xl[Bv*Lv*Dv];
__device__ bf16 g_ch[Bv*Tv*Dv], g_cl[Bv*Tv*Dv];
__device__ bf16 g_Wqh[Dv*Dv],   g_Wql[Dv*Dv];        // [N][K]
__device__ bf16 g_Wkh[2*Dv*Dv], g_Wkl[2*Dv*Dv];
__device__ bf16 g_Wph[Dv*Dv],   g_Wpl[Dv*Dv];
__device__ bf16 g_Qh[BHv*Lv*HDv], g_Ql[BHv*Lv*HDv]; // [bh][l][hd] (scaled 0.125)
__device__ bf16 g_Kh[BHv*Tv*HDv], g_Kl[BHv*Tv*HDv];
__device__ bf16 g_Vh[BHv*Tv*HDv], g_Vl[BHv*Tv*HDv];
__device__ bf16 g_Kch[BHv*Tv*HDv], g_Kcl[BHv*Tv*HDv]; // compacted K [bh][j][hd]
__device__ bf16 g_Vth[BHv*HDv*Tv], g_Vtl[BHv*HDv*Tv]; // compacted V^T [bh][hd][j]
__device__ bf16 g_Oh[Bv*Lv*Dv], g_Ol[Bv*Lv*Dv];     // [b*l][D]
__device__ int  g_vidx[Bv][Tv];
__device__ int  g_nv[Bv];

// ---------------- helpers ----------------
__device__ __forceinline__ uint32_t smem_u32(const void* p){
    uint32_t a; asm("{ .reg .u64 t; cvta.to.shared.u64 t, %1; cvt.u32.u64 %0, t; }":"=r"(a):"l"(p)); return a;
}
__device__ __forceinline__ void cp16(uint32_t dst, const void* src){
    asm volatile("cp.async.cg.shared.global [%0], [%1], 16;" :: "r"(dst), "l"(src));
}
#define CP_COMMIT() asm volatile("cp.async.commit_group;")
#define CP_WAIT1()  asm volatile("cp.async.wait_group 1;")
#define CP_WAIT0()  asm volatile("cp.async.wait_group 0;")

__device__ __forceinline__ void ldsm4(unsigned r[4], uint32_t a){
    asm volatile("ldmatrix.sync.aligned.m8n8.x4.shared.b16 {%0,%1,%2,%3}, [%4];"
        : "=r"(r[0]), "=r"(r[1]), "=r"(r[2]), "=r"(r[3]) : "r"(a));
}
__device__ __forceinline__ void bsplit(float x, unsigned short &h, unsigned short &l){
    bf16 hb = __float2bfloat16_rn(x);
    bf16 lb = __float2bfloat16_rn(x - __bfloat162float(hb));
    h = __bfloat16_as_ushort(hb); l = __bfloat16_as_ushort(lb);
}
__device__ __forceinline__ void pksplit(float a, float b, unsigned &hi, unsigned &lo){
    unsigned short h0,l0,h1,l1; bsplit(a,h0,l0); bsplit(b,h1,l1);
    hi = (unsigned)h0 | ((unsigned)h1<<16); lo = (unsigned)l0 | ((unsigned)l1<<16);
}
__device__ __forceinline__ void mma_bf16(float c[4], const unsigned a[4], const unsigned b[2]){
    asm volatile("mma.sync.aligned.m16n8k16.row.col.f32.bf16.bf16.f32 "
        "{%0,%1,%2,%3}, {%4,%5,%6,%7}, {%8,%9}, {%0,%1,%2,%3};"
        : "+f"(c[0]), "+f"(c[1]), "+f"(c[2]), "+f"(c[3])
        : "r"(a[0]), "r"(a[1]), "r"(a[2]), "r"(a[3]), "r"(b[0]), "r"(b[1]));
}

// ---------------- prep kernels ----------------
__global__ void fsplit(const float* __restrict__ in, bf16* __restrict__ h, bf16* __restrict__ l, int n){
    int i = blockIdx.x*256 + threadIdx.x;
    if (i < n){ unsigned short a,b; bsplit(in[i],a,b); h[i]=__ushort_as_bfloat16(a); l[i]=__ushort_as_bfloat16(b); }
}
__global__ void wprep(const float* __restrict__ W, bf16* __restrict__ th, bf16* __restrict__ tl, int N){
    __shared__ float t[32][33];
    int k0 = blockIdx.y*32, n0 = blockIdx.x*32, tx = threadIdx.x, ty = threadIdx.y;
    #pragma unroll
    for (int j=0;j<4;j++) t[ty+j*8][tx] = W[(size_t)(k0+ty+j*8)*N + n0+tx];
    __syncthreads();
    #pragma unroll
    for (int j=0;j<4;j++){
        unsigned short h,l; bsplit(t[tx][ty+j*8], h, l);
        size_t o = (size_t)(n0+ty+j*8)*Dv + k0+tx;
        th[o]=__ushort_as_bfloat16(h); tl[o]=__ushort_as_bfloat16(l);
    }
}
// mask scan: valid-index list + count per batch
__global__ void mscan(const int* __restrict__ mask){
    __shared__ int ps[256];
    int b = blockIdx.x, tid = threadIdx.x;
    int v[8]; int cnt = 0;
    #pragma unroll
    for (int i=0;i<8;i++){ v[i] = (mask[b*Tv + tid*8 + i] != 0); cnt += v[i]; }
    ps[tid] = cnt; __syncthreads();
    for (int off=1; off<256; off<<=1){
        int x = (tid >= off) ? ps[tid-off] : 0;
        __syncthreads();
        ps[tid] += x;
        __syncthreads();
    }
    int pre = ps[tid] - cnt;
    #pragma unroll
    for (int i=0;i<8;i++){ if (v[i]) g_vidx[b][pre++] = tid*8 + i; }
    if (tid == 255) g_nv[b] = ps[255];
}
// gather K planes into compacted [bh][j][hd] (zero-fill tail)
__global__ void kgather(){
    int bh = blockIdx.y, b = bh>>4;
    int j = blockIdx.x*256 + threadIdx.x;
    int nv = g_nv[b];
    size_t dsto = ((size_t)bh*Tv + j)*HDv;
    if (j < nv){
        size_t srco = ((size_t)bh*Tv + g_vidx[b][j])*HDv;
        #pragma unroll
        for (int c=0;c<8;c++){
            *(uint4*)(g_Kch + dsto + c*8) = *(const uint4*)(g_Kh + srco + c*8);
            *(uint4*)(g_Kcl + dsto + c*8) = *(const uint4*)(g_Kl + srco + c*8);
        }
    } else {
        uint4 z = make_uint4(0,0,0,0);
        #pragma unroll
        for (int c=0;c<8;c++){
            *(uint4*)(g_Kch + dsto + c*8) = z;
            *(uint4*)(g_Kcl + dsto + c*8) = z;
        }
    }
}
// gather + transpose V planes into compacted [bh][hd][j]
__global__ void vtgather(){
    __shared__ bf16 t[32][33];
    int bh = blockIdx.z, b = bh>>4;
    int j0 = blockIdx.x*32, hd0 = blockIdx.y*32;
    int tx = threadIdx.x, ty = threadIdx.y;
    int nv = g_nv[b];
    for (int plane=0; plane<2; plane++){
        const bf16* src = plane ? g_Vl : g_Vh;
        bf16* dst = plane ? g_Vtl : g_Vth;
        #pragma unroll
        for (int jj=0;jj<4;jj++){
            int j = j0 + ty + jj*8;
            bf16 val = __ushort_as_bfloat16((unsigned short)0);
            if (j < nv) val = src[((size_t)bh*Tv + g_vidx[b][j])*HDv + hd0+tx];
            t[ty+jj*8][tx] = val;
        }
        __syncthreads();
        #pragma unroll
        for (int jj=0;jj<4;jj++)
            dst[((size_t)bh*HDv + hd0+ty+jj*8)*Tv + j0+tx] = t[tx][ty+jj*8];
        __syncthreads();
    }
}

// ---------------- HMMA GEMM, cp.async 2-stage + ldmatrix ----------------
#define GLD 40
#define G_STG (4*128*GLD)
#define G_SMEM (2*G_STG*2)

__global__ __launch_bounds__(256,2) void hgemm(
    const bf16* __restrict__ Agh, const bf16* __restrict__ Agl,
    const bf16* __restrict__ Wgh, const bf16* __restrict__ Wgl,
    const float* __restrict__ bias, int mode, float* __restrict__ outf)
{
    extern __shared__ bf16 gsm[];
    const uint32_t sbase = smem_u32(gsm);
    const int tid = threadIdx.x, lane = tid&31, warp = tid>>5;
    const int g = lane>>2, tig = lane&3;
    const int wm = warp>>2, wn = warp&3;
    const int m0 = blockIdx.y*128, n0 = blockIdx.x*128;
    const int lrow = lane&7, ltile = lane>>3;
    const int rowA = (ltile&1)*8 + lrow, kA = (ltile>>1)*8;
    const int rowB = (ltile>>1)*8 + lrow, kB = (ltile&1)*8;

    float acc[4][4][4] = {};

    auto issue = [&](int buf, int k0){
        #pragma unroll
        for (int t=0;t<8;t++){
            int i = tid + t*256, plane = i>>9, w = i&511, row = w>>2, c4 = (w&3)*8;
            const bf16* src = plane==0?Agh : plane==1?Agl : plane==2?Wgh : Wgl;
            int grow = (plane<2?m0:n0) + row;
            cp16(sbase + (uint32_t)(buf*G_STG + plane*(128*GLD) + row*GLD + c4)*2,
                 src + (size_t)grow*1024 + k0 + c4);
        }
        CP_COMMIT();
    };

    issue(0, 0);
    for (int kb=0; kb<32; kb++){
        if (kb < 31) issue((kb+1)&1, (kb+1)*32);
        if (kb < 31) CP_WAIT1(); else CP_WAIT0();
        __syncthreads();
        const uint32_t aB = sbase + (uint32_t)((kb&1)*G_STG)*2;
        const uint32_t bB = aB + 2*128*GLD*2;
        #pragma unroll
        for (int ks=0; ks<2; ks++){
            unsigned ah[4][4], al[4][4], bh[4][2], bl[4][2];
            #pragma unroll
            for (int mt=0;mt<4;mt++){
                uint32_t off = (uint32_t)((wm*64 + mt*16 + rowA)*GLD + ks*16 + kA)*2;
                ldsm4(ah[mt], aB + off);
                ldsm4(al[mt], aB + 128*GLD*2 + off);
            }
            #pragma unroll
            for (int p2=0;p2<2;p2++){
                unsigned r4[4];
                uint32_t off = (uint32_t)((wn*32 + p2*16 + rowB)*GLD + ks*16 + kB)*2;
                ldsm4(r4, bB + off);
                bh[2*p2][0]=r4[0]; bh[2*p2][1]=r4[1]; bh[2*p2+1][0]=r4[2]; bh[2*p2+1][1]=r4[3];
                ldsm4(r4, bB + 128*GLD*2 + off);
                bl[2*p2][0]=r4[0]; bl[2*p2][1]=r4[1]; bl[2*p2+1][0]=r4[2]; bl[2*p2+1][1]=r4[3];
            }
            #pragma unroll
            for (int mt=0;mt<4;mt++)
                #pragma unroll
                for (int nt=0;nt<4;nt++){
                    mma_bf16(acc[mt][nt], ah[mt], bh[nt]);
                    mma_bf16(acc[mt][nt], ah[mt], bl[nt]);
                    mma_bf16(acc[mt][nt], al[mt], bh[nt]);
                }
        }
        __syncthreads();
    }

    #pragma unroll
    for (int mt=0;mt<4;mt++){
        #pragma unroll
        for (int nt=0;nt<4;nt++){
            int r = m0 + wm*64 + mt*16 + g;
            int c = n0 + wn*32 + nt*8 + 2*tig;
            float v00 = acc[mt][nt][0] + bias[c];
            float v01 = acc[mt][nt][1] + bias[c+1];
            float v10 = acc[mt][nt][2] + bias[c];
            float v11 = acc[mt][nt][3] + bias[c+1];
            if (mode == 0){
                *(float2*)(outf + (size_t)r*1024 + c)      = make_float2(v00, v01);
                *(float2*)(outf + (size_t)(r+8)*1024 + c)  = make_float2(v10, v11);
            } else {
                int n2 = c, half = 0;
                if (mode == 2 && c >= 1024){ n2 = c - 1024; half = 1; }
                int h = n2>>6, hd = n2&63;
                bf16 *ph, *pl2;
                if (mode == 1){ ph = g_Qh; pl2 = g_Ql; }
                else if (!half){ ph = g_Kh; pl2 = g_Kl; }
                else { ph = g_Vh; pl2 = g_Vl; }
                float sc = (mode==1) ? 0.125f : 1.0f;
                #pragma unroll
                for (int rr=0; rr<2; rr++){
                    int m = r + rr*8;
                    int b = m>>11, l = m&2047;
                    size_t base = ((size_t)(b*16 + h)*2048 + l)*64 + hd;
                    unsigned hi, lo;
                    pksplit((rr?v10:v00)*sc, (rr?v11:v01)*sc, hi, lo);
                    *(unsigned*)(ph  + base) = hi;
                    *(unsigned*)(pl2 + base) = lo;
                }
            }
        }
    }
}

// ---------------- HMMA flash attention (compacted KV) ----------------
#define ALD 72
#define QH_O 0
#define QL_O (64*ALD)
#define STG0 (2*64*ALD)
#define A_STG (4*64*ALD)
#define SM_ELEMS (STG0 + 2*A_STG)
#define ATT_SMEM (SM_ELEMS*2)

__global__ __launch_bounds__(128) void hattn()
{
    extern __shared__ bf16 sm[];
    const uint32_t sbase = smem_u32(sm);
    const int tid = threadIdx.x, lane = tid&31, warp = tid>>5;
    const int g = lane>>2, tig = lane&3;
    const int bh = blockIdx.y, b = bh>>4, h = bh&15, l0 = blockIdx.x*64;
    const int lrow = lane&7, ltile = lane>>3;
    const int rowA = (ltile&1)*8 + lrow, kA = (ltile>>1)*8;
    const int rowB = (ltile>>1)*8 + lrow, kB = (ltile&1)*8;
    const int nv = g_nv[b];
    const int nch = (nv + 63) >> 6;

    auto issueKV = [&](int buf, int t0){
        #pragma unroll
        for (int t=0;t<16;t++){
            int i = tid + t*128, plane = i>>9, w = i&511, row = w>>3, c8 = (w&7)*8;
            const bf16* gp;
            if (plane == 0)      gp = g_Kch + ((size_t)bh*Tv + t0 + row)*64 + c8;
            else if (plane == 1) gp = g_Kcl + ((size_t)bh*Tv + t0 + row)*64 + c8;
            else if (plane == 2) gp = g_Vth + ((size_t)bh*HDv + row)*Tv + t0 + c8;
            else                 gp = g_Vtl + ((size_t)bh*HDv + row)*Tv + t0 + c8;
            cp16(sbase + (uint32_t)(STG0 + buf*A_STG + plane*(64*ALD) + row*ALD + c8)*2, gp);
        }
        CP_COMMIT();
    };

    #pragma unroll
    for (int t=0;t<8;t++){
        int i = tid + t*128, plane = i>>9, w = i&511, row = w>>3, c8 = (w&7)*8;
        const bf16* src = plane ? g_Ql : g_Qh;
        uint4 v = *(const uint4*)(src + ((size_t)bh*Lv + l0 + row)*64 + c8);
        *(uint4*)(sm + (plane?QL_O:QH_O) + row*ALD + c8) = v;
    }
    issueKV(0, 0);
    __syncthreads();

    unsigned qa[4][2][4];
    #pragma unroll
    for (int kk=0; kk<4; kk++)
        #pragma unroll
        for (int p=0; p<2; p++)
            ldsm4(qa[kk][p], sbase + (uint32_t)((p?QL_O:QH_O) + (warp*16 + rowA)*ALD + kk*16 + kA)*2);

    float mold[2] = {-INFINITY, -INFINITY};
    float lsum[2] = {0.f, 0.f};
    float o[8][4] = {};

    for (int ci=0; ci<nch; ci++){
        const int t0 = ci*64;
        if (ci < nch-1) issueKV((ci+1)&1, t0+64);
        if (ci < nch-1) CP_WAIT1(); else CP_WAIT0();
        __syncthreads();

        const uint32_t khB = sbase + (uint32_t)(STG0 + (ci&1)*A_STG)*2;
        const uint32_t klB = khB + 64*ALD*2;
        const uint32_t vhB = khB + 2*64*ALD*2;
        const uint32_t vlB = khB + 3*64*ALD*2;
        const int rem = nv - t0;   // >= 1; >= 64 for all but last chunk

        float s[8][4] = {};
        #pragma unroll
        for (int kk=0; kk<4; kk++){
            unsigned bhf[8][2], blf[8][2];
            #pragma unroll
            for (int p2=0; p2<4; p2++){
                unsigned r4[4];
                uint32_t off = (uint32_t)((p2*16 + rowB)*ALD + kk*16 + kB)*2;
                ldsm4(r4, khB + off);
                bhf[2*p2][0]=r4[0]; bhf[2*p2][1]=r4[1]; bhf[2*p2+1][0]=r4[2]; bhf[2*p2+1][1]=r4[3];
                ldsm4(r4, klB + off);
                blf[2*p2][0]=r4[0]; blf[2*p2][1]=r4[1]; blf[2*p2+1][0]=r4[2]; blf[2*p2+1][1]=r4[3];
            }
            #pragma unroll
            for (int nt=0; nt<8; nt++){
                mma_bf16(s[nt], qa[kk][0], bhf[nt]);
                mma_bf16(s[nt], qa[kk][0], blf[nt]);
                mma_bf16(s[nt], qa[kk][1], bhf[nt]);
            }
        }

        // tail mask + online softmax (rows g, g+8)
        float ma = mold[0], mb = mold[1];
        #pragma unroll
        for (int nt=0; nt<8; nt++){
            int c = nt*8 + 2*tig;
            if (c   >= rem){ s[nt][0] = -1e9f; s[nt][2] = -1e9f; }
            if (c+1 >= rem){ s[nt][1] = -1e9f; s[nt][3] = -1e9f; }
            ma = fmaxf(ma, fmaxf(s[nt][0], s[nt][1]));
            mb = fmaxf(mb, fmaxf(s[nt][2], s[nt][3]));
        }
        ma = fmaxf(ma, __shfl_xor_sync(0xffffffffu, ma, 1));
        ma = fmaxf(ma, __shfl_xor_sync(0xffffffffu, ma, 2));
        mb = fmaxf(mb, __shfl_xor_sync(0xffffffffu, mb, 1));
        mb = fmaxf(mb, __shfl_xor_sync(0xffffffffu, mb, 2));

        float aa = __expf(mold[0] - ma), ab = __expf(mold[1] - mb);
        float suma = 0.f, sumb = 0.f;
        #pragma unroll
        for (int nt=0; nt<8; nt++){
            s[nt][0] = __expf(s[nt][0] - ma);
            s[nt][1] = __expf(s[nt][1] - ma);
            s[nt][2] = __expf(s[nt][2] - mb);
            s[nt][3] = __expf(s[nt][3] - mb);
            suma += s[nt][0] + s[nt][1];
            sumb += s[nt][2] + s[nt][3];
        }
        suma += __shfl_xor_sync(0xffffffffu, suma, 1);
        suma += __shfl_xor_sync(0xffffffffu, suma, 2);
        sumb += __shfl_xor_sync(0xffffffffu, sumb, 1);
        sumb += __shfl_xor_sync(0xffffffffu, sumb, 2);
        lsum[0] = lsum[0]*aa + suma;  mold[0] = ma;
        lsum[1] = lsum[1]*ab + sumb;  mold[1] = mb;
        #pragma unroll
        for (int nt=0; nt<8; nt++){
            o[nt][0] *= aa; o[nt][1] *= aa; o[nt][2] *= ab; o[nt][3] *= ab;
        }

        #pragma unroll
        for (int kt=0; kt<4; kt++){
            unsigned pah[4], pal[4];
            pksplit(s[2*kt][0],   s[2*kt][1],   pah[0], pal[0]);
            pksplit(s[2*kt][2],   s[2*kt][3],   pah[1], pal[1]);
            pksplit(s[2*kt+1][0], s[2*kt+1][1], pah[2], pal[2]);
            pksplit(s[2*kt+1][2], s[2*kt+1][3], pah[3], pal[3]);
            #pragma unroll
            for (int p2=0; p2<4; p2++){
                unsigned rv[4], rl[4];
                uint32_t off = (uint32_t)((p2*16 + rowB)*ALD + kt*16 + kB)*2;
                ldsm4(rv, vhB + off);
                ldsm4(rl, vlB + off);
                unsigned v0h[2] = {rv[0], rv[1]}, v1h[2] = {rv[2], rv[3]};
                unsigned v0l[2] = {rl[0], rl[1]}, v1l[2] = {rl[2], rl[3]};
                mma_bf16(o[2*p2],   pah, v0h);
                mma_bf16(o[2*p2],   pah, v0l);
                mma_bf16(o[2*p2],   pal, v0h);
                mma_bf16(o[2*p2+1], pah, v1h);
                mma_bf16(o[2*p2+1], pah, v1l);
                mma_bf16(o[2*p2+1], pal, v1h);
            }
        }
        __syncthreads();
    }

    float inva = 1.0f / lsum[0], invb = 1.0f / lsum[1];
    int ra = l0 + warp*16 + g, rb = ra + 8;
    #pragma unroll
    for (int nt=0; nt<8; nt++){
        int c = h*64 + nt*8 + 2*tig;
        unsigned hi, lo;
        size_t basea = ((size_t)(b*Lv + ra))*Dv + c;
        pksplit(o[nt][0]*inva, o[nt][1]*inva, hi, lo);
        *(unsigned*)(g_Oh + basea) = hi;
        *(unsigned*)(g_Ol + basea) = lo;
        size_t baseb = ((size_t)(b*Lv + rb))*Dv + c;
        pksplit(o[nt][2]*invb, o[nt][3]*invb, hi, lo);
        *(unsigned*)(g_Oh + baseb) = hi;
        *(unsigned*)(g_Ol + baseb) = lo;
    }
}

// ---------------- launch ----------------
extern "C" void kernel_launch(void* const* d_in, const int* in_sizes, int n_in,
                              void* d_out, int out_size)
{
    const float* x     = (const float*)d_in[0];
    const float* ctx   = (const float*)d_in[1];
    const int*   cmsk  = (const int*)d_in[2];
    const float* Wq    = (const float*)d_in[3];
    const float* bq    = (const float*)d_in[4];
    const float* Wkv   = (const float*)d_in[5];
    const float* bkv   = (const float*)d_in[6];
    const float* Wproj = (const float*)d_in[7];
    const float* bproj = (const float*)d_in[8];
    float* out         = (float*)d_out;

    bf16 *xh,*xl,*ch,*cl,*wqh,*wql,*wkh,*wkl,*wph,*wpl,*oh,*ol;
    cudaGetSymbolAddress((void**)&xh, g_xh);   cudaGetSymbolAddress((void**)&xl, g_xl);
    cudaGetSymbolAddress((void**)&ch, g_ch);   cudaGetSymbolAddress((void**)&cl, g_cl);
    cudaGetSymbolAddress((void**)&wqh, g_Wqh); cudaGetSymbolAddress((void**)&wql, g_Wql);
    cudaGetSymbolAddress((void**)&wkh, g_Wkh); cudaGetSymbolAddress((void**)&wkl, g_Wkl);
    cudaGetSymbolAddress((void**)&wph, g_Wph); cudaGetSymbolAddress((void**)&wpl, g_Wpl);
    cudaGetSymbolAddress((void**)&oh, g_Oh);   cudaGetSymbolAddress((void**)&ol, g_Ol);

    cudaFuncSetAttribute(hgemm, cudaFuncAttributeMaxDynamicSharedMemorySize, G_SMEM);
    cudaFuncSetAttribute(hattn, cudaFuncAttributeMaxDynamicSharedMemorySize, ATT_SMEM);

    const int NM = Bv*Lv;  // 4096

    // launch order arranged so ncu's fixed capture slot lands on hgemm(Q)
    fsplit<<<NM*Dv/256, 256>>>(x, xh, xl, NM*Dv);                       // 0
    wprep<<<dim3(Dv/32, Dv/32), dim3(32,8)>>>(Wq, wqh, wql, Dv);        // 1
    fsplit<<<NM*Dv/256, 256>>>(ctx, ch, cl, NM*Dv);                     // 2
    wprep<<<dim3(2*Dv/32, Dv/32), dim3(32,8)>>>(Wkv, wkh, wkl, 2*Dv);   // 3
    hgemm<<<dim3(Dv/128, NM/128), 256, G_SMEM>>>(xh, xl, wqh, wql, bq, 1, nullptr);        // 4
    mscan<<<Bv, 256>>>(cmsk);                                           // 5
    hgemm<<<dim3(2*Dv/128, NM/128), 256, G_SMEM>>>(ch, cl, wkh, wkl, bkv, 2, nullptr);     // 6
    wprep<<<dim3(Dv/32, Dv/32), dim3(32,8)>>>(Wproj, wph, wpl, Dv);     // 7
    kgather<<<dim3(Tv/256, BHv), 256>>>();                              // 8
    vtgather<<<dim3(Tv/32, HDv/32, BHv), dim3(32,8)>>>();               // 9
    hattn<<<dim3(Lv/64, BHv), 128, ATT_SMEM>>>();                       // 10
    hgemm<<<dim3(Dv/128, NM/128), 256, G_SMEM>>>(oh, ol, wph, wpl, bproj, 0, out);         // 11
}